// round 7
// baseline (speedup 1.0000x reference)
#include <cuda_runtime.h>
#include <cuda_bf16.h>
#include <cuda_fp16.h>
#include <cstdint>

#define N_NODES 50000
#define N_EDGES 800000
#define DIM 128
#define NEG_SLOPE 0.01f

#define SCAN_BLK 1024
#define SCAN_NBLK ((N_NODES + SCAN_BLK - 1) / SCAN_BLK)   // 49

// ---------------- scratch (device globals; no allocation allowed) ----------
__device__ int    g_cnt[N_NODES];
__device__ int    g_off[N_NODES + 1];
__device__ int    g_cur[N_NODES];
__device__ int    g_part[64];
__device__ int    g_ssrc[N_EDGES];
__device__ __half g_xh[N_NODES * DIM];      // fp16 copy of x
__device__ __half g_hah[N_NODES * DIM];     // fp16 ha_src
__device__ float  g_hmean[N_NODES * DIM];
__device__ float  g_ha_dst[N_NODES * DIM];

// ---------------- k0: zero histogram counters ------------------------------
__global__ void zero_cnt_kernel() {
    int i = blockIdx.x * blockDim.x + threadIdx.x;
    if (i < N_NODES) g_cnt[i] = 0;
}

// ---------------- k1: x -> fp16 copy ---------------------------------------
__global__ void x2h_kernel(const float* __restrict__ x) {
    int idx = (blockIdx.x * blockDim.x + threadIdx.x) * 4;
    if (idx < N_NODES * DIM) {
        float4 v = *(const float4*)&x[idx];
        __half2 h0 = __floats2half2_rn(v.x, v.y);
        __half2 h1 = __floats2half2_rn(v.z, v.w);
        *(__half2*)&g_xh[idx]     = h0;
        *(__half2*)&g_xh[idx + 2] = h1;
    }
}

// ---------------- k2: degree histogram over dst (ILP-4) --------------------
__global__ void hist_kernel(const int* __restrict__ dst) {
    int base = (blockIdx.x * blockDim.x + threadIdx.x) * 4;
    if (base + 3 < N_EDGES) {
        int4 d4 = *(const int4*)&dst[base];
        atomicAdd(&g_cnt[d4.x], 1);
        atomicAdd(&g_cnt[d4.y], 1);
        atomicAdd(&g_cnt[d4.z], 1);
        atomicAdd(&g_cnt[d4.w], 1);
    } else {
        for (int e = base; e < N_EDGES; e++) atomicAdd(&g_cnt[dst[e]], 1);
    }
}

// ---------------- k3a: per-block sums --------------------------------------
__global__ __launch_bounds__(SCAN_BLK) void scan_a_kernel() {
    __shared__ int sh[32];
    int tid = threadIdx.x;
    int i = blockIdx.x * SCAN_BLK + tid;
    int v = (i < N_NODES) ? g_cnt[i] : 0;
#pragma unroll
    for (int off = 16; off > 0; off >>= 1) v += __shfl_xor_sync(0xFFFFFFFFu, v, off);
    if ((tid & 31) == 0) sh[tid >> 5] = v;
    __syncthreads();
    if (tid < 32) {
        int s = sh[tid];
#pragma unroll
        for (int off = 16; off > 0; off >>= 1) s += __shfl_xor_sync(0xFFFFFFFFu, s, off);
        if (tid == 0) g_part[blockIdx.x] = s;
    }
}

// ------- k3b: block scan (warp-shuffle) + redundant partial sum -> offsets -
__global__ __launch_bounds__(SCAN_BLK) void scan_c_kernel() {
    __shared__ int warpsum[32];
    __shared__ int blockOff;
    int tid = threadIdx.x;
    int lane = tid & 31, wid = tid >> 5;
    int i = blockIdx.x * SCAN_BLK + tid;
    int v = (i < N_NODES) ? g_cnt[i] : 0;
    int incl = v;
#pragma unroll
    for (int off = 1; off < 32; off <<= 1) {
        int t = __shfl_up_sync(0xFFFFFFFFu, incl, off);
        if (lane >= off) incl += t;
    }
    if (lane == 31) warpsum[wid] = incl;
    if (tid == 0) {
        int s = 0;
        for (int b = 0; b < (int)blockIdx.x; b++) s += g_part[b];
        blockOff = s;
    }
    __syncthreads();
    if (wid == 0) {
        int s = (lane < 32) ? warpsum[lane] : 0;
#pragma unroll
        for (int off = 1; off < 32; off <<= 1) {
            int t = __shfl_up_sync(0xFFFFFFFFu, s, off);
            if (lane >= off) s += t;
        }
        warpsum[lane] = s;
    }
    __syncthreads();
    int warpExcl = (wid > 0) ? warpsum[wid - 1] : 0;
    int excl = incl - v + warpExcl + blockOff;
    if (i < N_NODES) {
        g_off[i] = excl;
        g_cur[i] = excl;
    }
    if (i == 0) g_off[N_NODES] = N_EDGES;
}

// ---------------- k4: scatter edges into dst-sorted order (ILP-4) ----------
__global__ void scatter_kernel(const int* __restrict__ src,
                               const int* __restrict__ dst) {
    int base = (blockIdx.x * blockDim.x + threadIdx.x) * 4;
    if (base + 3 < N_EDGES) {
        int4 d4 = *(const int4*)&dst[base];
        int4 s4 = *(const int4*)&src[base];
        int p0 = atomicAdd(&g_cur[d4.x], 1);
        int p1 = atomicAdd(&g_cur[d4.y], 1);
        int p2 = atomicAdd(&g_cur[d4.z], 1);
        int p3 = atomicAdd(&g_cur[d4.w], 1);
        g_ssrc[p0] = s4.x;
        g_ssrc[p1] = s4.y;
        g_ssrc[p2] = s4.z;
        g_ssrc[p3] = s4.w;
    } else {
        for (int e = base; e < N_EDGES; e++) {
            int p = atomicAdd(&g_cur[dst[e]], 1);
            g_ssrc[p] = src[e];
        }
    }
}

// ---------------- k5: mean aggregation (fp16 gather), warp per dst ---------
__device__ __forceinline__ float4 ldh4(const __half* p) {
    uint2 raw = *(const uint2*)p;
    __half2 h0 = *(__half2*)&raw.x;
    __half2 h1 = *(__half2*)&raw.y;
    float2 f0 = __half22float2(h0);
    float2 f1 = __half22float2(h1);
    return make_float4(f0.x, f0.y, f1.x, f1.y);
}

__global__ __launch_bounds__(256) void agg_kernel() {
    int warp = (blockIdx.x * blockDim.x + threadIdx.x) >> 5;
    int lane = threadIdx.x & 31;
    if (warp >= N_NODES) return;
    int beg = g_off[warp];
    int end = g_off[warp + 1];
    float4 acc = make_float4(0.f, 0.f, 0.f, 0.f);
    int p = beg;
    for (; p + 3 < end; p += 4) {
        int s0 = g_ssrc[p], s1 = g_ssrc[p + 1], s2 = g_ssrc[p + 2], s3 = g_ssrc[p + 3];
        float4 v0 = ldh4(&g_xh[(long long)s0 * DIM + lane * 4]);
        float4 v1 = ldh4(&g_xh[(long long)s1 * DIM + lane * 4]);
        float4 v2 = ldh4(&g_xh[(long long)s2 * DIM + lane * 4]);
        float4 v3 = ldh4(&g_xh[(long long)s3 * DIM + lane * 4]);
        acc.x += v0.x + v1.x + v2.x + v3.x;
        acc.y += v0.y + v1.y + v2.y + v3.y;
        acc.z += v0.z + v1.z + v2.z + v3.z;
        acc.w += v0.w + v1.w + v2.w + v3.w;
    }
    for (; p < end; p++) {
        int s = g_ssrc[p];
        float4 v = ldh4(&g_xh[(long long)s * DIM + lane * 4]);
        acc.x += v.x; acc.y += v.y; acc.z += v.z; acc.w += v.w;
    }
    float r = 1.0f / (float)max(end - beg, 1);
    float4 o = make_float4(acc.x * r, acc.y * r, acc.z * r, acc.w * r);
    *(float4*)&g_hmean[(long long)warp * DIM + lane * 4] = o;
}

// ---------------- tf32x3 tensor-core GEMM ----------------------------------
__device__ __forceinline__ uint32_t f2tf(float f) {
    uint32_t u;
    asm("cvt.rna.tf32.f32 %0, %1;" : "=r"(u) : "f"(f));
    return u;
}

__device__ __forceinline__ void mma_tf32(float* c, const uint32_t* a, const uint32_t* b) {
    asm volatile(
        "mma.sync.aligned.m16n8k8.row.col.f32.tf32.tf32.f32 "
        "{%0,%1,%2,%3}, {%4,%5,%6,%7}, {%8,%9}, {%0,%1,%2,%3};"
        : "+f"(c[0]), "+f"(c[1]), "+f"(c[2]), "+f"(c[3])
        : "r"(a[0]), "r"(a[1]), "r"(a[2]), "r"(a[3]), "r"(b[0]), "r"(b[1]));
}

#define SMSTRIDE 132
#define GEMM_SMEM (2 * 128 * SMSTRIDE * 4)

// y==0: A=x, W=src_w -> g_hah (fp16). y==1: A=hmean, W=dst_w -> g_ha_dst (fp32).
__global__ __launch_bounds__(256) void gemm_tc_kernel(
    const float* __restrict__ x, const float* __restrict__ hmean,
    const float* __restrict__ src_w, const float* __restrict__ dst_w,
    const float* __restrict__ src_b, const float* __restrict__ dst_b) {
    extern __shared__ float sm[];
    float* As = sm;
    float* Ws = sm + 128 * SMSTRIDE;

    const float* A    = (blockIdx.y == 0) ? x     : hmean;
    const float* W    = (blockIdx.y == 0) ? src_w : dst_w;
    const float* bias = (blockIdx.y == 0) ? src_b : dst_b;

    int tid = threadIdx.x;
    int rowBase = blockIdx.x * 128;

#pragma unroll
    for (int it = 0; it < 16; it++) {
        int idx = tid + it * 256;
        int r = idx >> 5;
        int c = (idx & 31) * 4;
        float4 v = make_float4(0.f, 0.f, 0.f, 0.f);
        if (rowBase + r < N_NODES)
            v = *(const float4*)&A[(long long)(rowBase + r) * DIM + c];
        *(float4*)&As[r * SMSTRIDE + c] = v;
        float4 wv = *(const float4*)&W[(long long)r * DIM + c];
        *(float4*)&Ws[r * SMSTRIDE + c] = wv;
    }
    __syncthreads();

    int wid = tid >> 5, lane = tid & 31;
    int g = lane >> 2, t = lane & 3;
    int warpM = wid & 3, warpN = wid >> 2;
    int wrow = warpM * 32, wcol = warpN * 64;

    float acc[2][8][4];
#pragma unroll
    for (int mt = 0; mt < 2; mt++)
#pragma unroll
        for (int nt = 0; nt < 8; nt++)
#pragma unroll
            for (int j = 0; j < 4; j++) acc[mt][nt][j] = 0.0f;

    for (int kt = 0; kt < 16; kt++) {
        int k0 = kt * 8;
        uint32_t ahi[2][4], alo[2][4];
#pragma unroll
        for (int mt = 0; mt < 2; mt++) {
            int r0 = wrow + mt * 16;
            float a0 = As[(r0 + g) * SMSTRIDE + k0 + t];
            float a1 = As[(r0 + g + 8) * SMSTRIDE + k0 + t];
            float a2 = As[(r0 + g) * SMSTRIDE + k0 + t + 4];
            float a3 = As[(r0 + g + 8) * SMSTRIDE + k0 + t + 4];
            ahi[mt][0] = f2tf(a0); alo[mt][0] = f2tf(a0 - __uint_as_float(ahi[mt][0]));
            ahi[mt][1] = f2tf(a1); alo[mt][1] = f2tf(a1 - __uint_as_float(ahi[mt][1]));
            ahi[mt][2] = f2tf(a2); alo[mt][2] = f2tf(a2 - __uint_as_float(ahi[mt][2]));
            ahi[mt][3] = f2tf(a3); alo[mt][3] = f2tf(a3 - __uint_as_float(ahi[mt][3]));
        }
        uint32_t bhi[8][2], blo[8][2];
#pragma unroll
        for (int nt = 0; nt < 8; nt++) {
            int col = wcol + nt * 8 + g;
            float b0 = Ws[(k0 + t) * SMSTRIDE + col];
            float b1 = Ws[(k0 + t + 4) * SMSTRIDE + col];
            bhi[nt][0] = f2tf(b0); blo[nt][0] = f2tf(b0 - __uint_as_float(bhi[nt][0]));
            bhi[nt][1] = f2tf(b1); blo[nt][1] = f2tf(b1 - __uint_as_float(bhi[nt][1]));
        }
#pragma unroll
        for (int mt = 0; mt < 2; mt++)
#pragma unroll
            for (int nt = 0; nt < 8; nt++) {
                mma_tf32(acc[mt][nt], ahi[mt], blo[nt]);
                mma_tf32(acc[mt][nt], alo[mt], bhi[nt]);
                mma_tf32(acc[mt][nt], ahi[mt], bhi[nt]);
            }
    }

    bool toHalf = (blockIdx.y == 0);
#pragma unroll
    for (int mt = 0; mt < 2; mt++) {
#pragma unroll
        for (int nt = 0; nt < 8; nt++) {
            int col = wcol + nt * 8 + 2 * t;
            float b0 = bias[col], b1 = bias[col + 1];
            int row0 = rowBase + wrow + mt * 16 + g;
            int row1 = row0 + 8;
            float c00 = acc[mt][nt][0] + b0, c01 = acc[mt][nt][1] + b1;
            float c10 = acc[mt][nt][2] + b0, c11 = acc[mt][nt][3] + b1;
            if (toHalf) {
                if (row0 < N_NODES)
                    *(__half2*)&g_hah[(long long)row0 * DIM + col] = __floats2half2_rn(c00, c01);
                if (row1 < N_NODES)
                    *(__half2*)&g_hah[(long long)row1 * DIM + col] = __floats2half2_rn(c10, c11);
            } else {
                if (row0 < N_NODES)
                    *(float2*)&g_ha_dst[(long long)row0 * DIM + col] = make_float2(c00, c01);
                if (row1 < N_NODES)
                    *(float2*)&g_ha_dst[(long long)row1 * DIM + col] = make_float2(c10, c11);
            }
        }
    }
}

// ------- k7: fused score + denom + weighted output (fp16 gathers) ----------
__global__ __launch_bounds__(256) void fused_out_kernel(
    const float* __restrict__ att_w,
    const float* __restrict__ att_b,
    float* __restrict__ out) {
    int warp = (blockIdx.x * blockDim.x + threadIdx.x) >> 5;
    int lane = threadIdx.x & 31;
    if (warp >= N_NODES) return;
    int beg = g_off[warp];
    int end = g_off[warp + 1];

    float4 b = *(const float4*)&g_ha_dst[(long long)warp * DIM + lane * 4];
    float4 w = *(const float4*)&att_w[lane * 4];
    float  c = att_b[0];

    float denom = 0.0f;
    float4 o = make_float4(0.f, 0.f, 0.f, 0.f);
    int p = beg;
    for (; p + 1 < end; p += 2) {
        int s0 = g_ssrc[p], s1 = g_ssrc[p + 1];
        float4 a0 = ldh4(&g_hah[(long long)s0 * DIM + lane * 4]);
        float4 a1 = ldh4(&g_hah[(long long)s1 * DIM + lane * 4]);
        float4 x0 = ldh4(&g_xh[(long long)s0 * DIM + lane * 4]);
        float4 x1 = ldh4(&g_xh[(long long)s1 * DIM + lane * 4]);
        float t0, t1;
        {
            float v0 = a0.x + b.x, v1 = a0.y + b.y, v2 = a0.z + b.z, v3 = a0.w + b.w;
            v0 = (v0 >= 0.f) ? v0 : v0 * NEG_SLOPE;
            v1 = (v1 >= 0.f) ? v1 : v1 * NEG_SLOPE;
            v2 = (v2 >= 0.f) ? v2 : v2 * NEG_SLOPE;
            v3 = (v3 >= 0.f) ? v3 : v3 * NEG_SLOPE;
            t0 = v0 * w.x + v1 * w.y + v2 * w.z + v3 * w.w;
        }
        {
            float v0 = a1.x + b.x, v1 = a1.y + b.y, v2 = a1.z + b.z, v3 = a1.w + b.w;
            v0 = (v0 >= 0.f) ? v0 : v0 * NEG_SLOPE;
            v1 = (v1 >= 0.f) ? v1 : v1 * NEG_SLOPE;
            v2 = (v2 >= 0.f) ? v2 : v2 * NEG_SLOPE;
            v3 = (v3 >= 0.f) ? v3 : v3 * NEG_SLOPE;
            t1 = v0 * w.x + v1 * w.y + v2 * w.z + v3 * w.w;
        }
#pragma unroll
        for (int off = 16; off > 0; off >>= 1) {
            t0 += __shfl_xor_sync(0xFFFFFFFFu, t0, off);
            t1 += __shfl_xor_sync(0xFFFFFFFFu, t1, off);
        }
        float sv0 = expf(t0 + c);
        float sv1 = expf(t1 + c);
        denom += sv0 + sv1;
        o.x += sv0 * x0.x + sv1 * x1.x;
        o.y += sv0 * x0.y + sv1 * x1.y;
        o.z += sv0 * x0.z + sv1 * x1.z;
        o.w += sv0 * x0.w + sv1 * x1.w;
    }
    for (; p < end; p++) {
        int s = g_ssrc[p];
        float4 a = ldh4(&g_hah[(long long)s * DIM + lane * 4]);
        float4 xv = ldh4(&g_xh[(long long)s * DIM + lane * 4]);
        float v0 = a.x + b.x, v1 = a.y + b.y, v2 = a.z + b.z, v3 = a.w + b.w;
        v0 = (v0 >= 0.f) ? v0 : v0 * NEG_SLOPE;
        v1 = (v1 >= 0.f) ? v1 : v1 * NEG_SLOPE;
        v2 = (v2 >= 0.f) ? v2 : v2 * NEG_SLOPE;
        v3 = (v3 >= 0.f) ? v3 : v3 * NEG_SLOPE;
        float t = v0 * w.x + v1 * w.y + v2 * w.z + v3 * w.w;
#pragma unroll
        for (int off = 16; off > 0; off >>= 1)
            t += __shfl_xor_sync(0xFFFFFFFFu, t, off);
        float sv = expf(t + c);
        denom += sv;
        o.x += sv * xv.x; o.y += sv * xv.y; o.z += sv * xv.z; o.w += sv * xv.w;
    }

    float rd = (end > beg) ? 1.0f / denom : 0.0f;
    float4 r = make_float4(o.x * rd, o.y * rd, o.z * rd, o.w * rd);
    *(float4*)&out[(long long)warp * DIM + lane * 4] = r;
}

// ---------------------------------------------------------------------------
extern "C" void kernel_launch(void* const* d_in, const int* in_sizes, int n_in,
                              void* d_out, int out_size) {
    const float* x       = (const float*)d_in[0];
    const int*   src_idx = (const int*)d_in[1];
    const int*   dst_idx = (const int*)d_in[2];
    const float* src_w   = (const float*)d_in[3];
    const float* src_b   = (const float*)d_in[4];
    const float* dst_w   = (const float*)d_in[5];
    const float* dst_b   = (const float*)d_in[6];
    const float* att_w   = (const float*)d_in[7];
    const float* att_b   = (const float*)d_in[8];
    float* out = (float*)d_out;

    (void)in_sizes; (void)n_in; (void)out_size;

    float* hmean_p;
    cudaGetSymbolAddress((void**)&hmean_p, g_hmean);

    cudaFuncSetAttribute(gemm_tc_kernel,
                         cudaFuncAttributeMaxDynamicSharedMemorySize, GEMM_SMEM);

    const int e4Blocks = (N_EDGES / 4 + 255) / 256;
    const int nodeWarpBlocks = (N_NODES * 32 + 255) / 256;

    zero_cnt_kernel<<<(N_NODES + 255) / 256, 256>>>();
    x2h_kernel<<<(N_NODES * DIM / 4 + 255) / 256, 256>>>(x);
    hist_kernel<<<e4Blocks, 256>>>(dst_idx);
    scan_a_kernel<<<SCAN_NBLK, SCAN_BLK>>>();
    scan_c_kernel<<<SCAN_NBLK, SCAN_BLK>>>();
    scatter_kernel<<<e4Blocks, 256>>>(src_idx, dst_idx);

    agg_kernel<<<nodeWarpBlocks, 256>>>();

    dim3 gemmGrid((N_NODES + 127) / 128, 2);
    gemm_tc_kernel<<<gemmGrid, 256, GEMM_SMEM>>>(
        x, hmean_p, src_w, dst_w, src_b, dst_b);

    fused_out_kernel<<<nodeWarpBlocks, 256>>>(att_w, att_b, out);
}

// round 8
// speedup vs baseline: 1.0133x; 1.0133x over previous
#include <cuda_runtime.h>
#include <cuda_bf16.h>
#include <cuda_fp16.h>
#include <cstdint>

#define N_NODES 50000
#define N_EDGES 800000
#define DIM 128
#define NEG_SLOPE 0.01f

#define SCAN_BLK 1024
#define SCAN_NBLK ((N_NODES + SCAN_BLK - 1) / SCAN_BLK)   // 49

// ---------------- scratch (device globals; no allocation allowed) ----------
__device__ int    g_cnt[N_NODES];
__device__ int    g_off[N_NODES + 1];
__device__ int    g_cur[N_NODES];
__device__ int    g_part[64];
__device__ int    g_ssrc[N_EDGES];
// interleaved per-node record: 32 chunks x 16B; chunk c = {x[4c..4c+3] fp16 (8B), ha_src[4c..4c+3] fp16 (8B)}
__device__ uint4  g_comb[N_NODES * 32];
__device__ __half g_xproj[N_NODES * DIM];   // fp16 x @ dst_w
__device__ float  g_ha_dst[N_NODES * DIM];  // fp32, = segment_mean(xproj[src])

// ---------------- k0: prep = zero cnt + x->fp16 into comb ------------------
__global__ void prep_kernel(const float* __restrict__ x) {
    int tid = blockIdx.x * blockDim.x + threadIdx.x;
    if (tid < N_NODES) g_cnt[tid] = 0;
    int i = tid * 4;
    if (i < N_NODES * DIM) {
        float4 v = *(const float4*)&x[i];
        __half2 h0 = __floats2half2_rn(v.x, v.y);
        __half2 h1 = __floats2half2_rn(v.z, v.w);
        int row = i >> 7;              // /128
        int chunk = (i & 127) >> 2;    // 0..31
        uint2 u = make_uint2(*(uint32_t*)&h0, *(uint32_t*)&h1);
        *(uint2*)&g_comb[row * 32 + chunk] = u;   // writes bytes [0:8) of chunk
    }
}

// ---------------- k1: degree histogram over dst (ILP-4) --------------------
__global__ void hist_kernel(const int* __restrict__ dst) {
    int base = (blockIdx.x * blockDim.x + threadIdx.x) * 4;
    if (base + 3 < N_EDGES) {
        int4 d4 = *(const int4*)&dst[base];
        atomicAdd(&g_cnt[d4.x], 1);
        atomicAdd(&g_cnt[d4.y], 1);
        atomicAdd(&g_cnt[d4.z], 1);
        atomicAdd(&g_cnt[d4.w], 1);
    } else {
        for (int e = base; e < N_EDGES; e++) atomicAdd(&g_cnt[dst[e]], 1);
    }
}

// ---------------- k2a: per-block sums --------------------------------------
__global__ __launch_bounds__(SCAN_BLK) void scan_a_kernel() {
    __shared__ int sh[32];
    int tid = threadIdx.x;
    int i = blockIdx.x * SCAN_BLK + tid;
    int v = (i < N_NODES) ? g_cnt[i] : 0;
#pragma unroll
    for (int off = 16; off > 0; off >>= 1) v += __shfl_xor_sync(0xFFFFFFFFu, v, off);
    if ((tid & 31) == 0) sh[tid >> 5] = v;
    __syncthreads();
    if (tid < 32) {
        int s = sh[tid];
#pragma unroll
        for (int off = 16; off > 0; off >>= 1) s += __shfl_xor_sync(0xFFFFFFFFu, s, off);
        if (tid == 0) g_part[blockIdx.x] = s;
    }
}

// ------- k2b: block scan (warp-shuffle) + redundant partial sum -> offsets -
__global__ __launch_bounds__(SCAN_BLK) void scan_c_kernel() {
    __shared__ int warpsum[32];
    __shared__ int blockOff;
    int tid = threadIdx.x;
    int lane = tid & 31, wid = tid >> 5;
    int i = blockIdx.x * SCAN_BLK + tid;
    int v = (i < N_NODES) ? g_cnt[i] : 0;
    int incl = v;
#pragma unroll
    for (int off = 1; off < 32; off <<= 1) {
        int t = __shfl_up_sync(0xFFFFFFFFu, incl, off);
        if (lane >= off) incl += t;
    }
    if (lane == 31) warpsum[wid] = incl;
    if (tid == 0) {
        int s = 0;
        for (int b = 0; b < (int)blockIdx.x; b++) s += g_part[b];
        blockOff = s;
    }
    __syncthreads();
    if (wid == 0) {
        int s = warpsum[lane];
#pragma unroll
        for (int off = 1; off < 32; off <<= 1) {
            int t = __shfl_up_sync(0xFFFFFFFFu, s, off);
            if (lane >= off) s += t;
        }
        warpsum[lane] = s;
    }
    __syncthreads();
    int warpExcl = (wid > 0) ? warpsum[wid - 1] : 0;
    int excl = incl - v + warpExcl + blockOff;
    if (i < N_NODES) {
        g_off[i] = excl;
        g_cur[i] = excl;
    }
    if (i == 0) g_off[N_NODES] = N_EDGES;
}

// ---------------- k3: scatter edges into dst-sorted order (ILP-4) ----------
__global__ void scatter_kernel(const int* __restrict__ src,
                               const int* __restrict__ dst) {
    int base = (blockIdx.x * blockDim.x + threadIdx.x) * 4;
    if (base + 3 < N_EDGES) {
        int4 d4 = *(const int4*)&dst[base];
        int4 s4 = *(const int4*)&src[base];
        int p0 = atomicAdd(&g_cur[d4.x], 1);
        int p1 = atomicAdd(&g_cur[d4.y], 1);
        int p2 = atomicAdd(&g_cur[d4.z], 1);
        int p3 = atomicAdd(&g_cur[d4.w], 1);
        g_ssrc[p0] = s4.x;
        g_ssrc[p1] = s4.y;
        g_ssrc[p2] = s4.z;
        g_ssrc[p3] = s4.w;
    } else {
        for (int e = base; e < N_EDGES; e++) {
            int p = atomicAdd(&g_cur[dst[e]], 1);
            g_ssrc[p] = src[e];
        }
    }
}

// ---------------- tf32x3 tensor-core GEMM (A = x always) -------------------
// y==0: W=src_w -> fp16 into g_comb ha-slots. y==1: W=dst_w -> fp16 g_xproj.
__device__ __forceinline__ uint32_t f2tf(float f) {
    uint32_t u;
    asm("cvt.rna.tf32.f32 %0, %1;" : "=r"(u) : "f"(f));
    return u;
}

__device__ __forceinline__ void mma_tf32(float* c, const uint32_t* a, const uint32_t* b) {
    asm volatile(
        "mma.sync.aligned.m16n8k8.row.col.f32.tf32.tf32.f32 "
        "{%0,%1,%2,%3}, {%4,%5,%6,%7}, {%8,%9}, {%0,%1,%2,%3};"
        : "+f"(c[0]), "+f"(c[1]), "+f"(c[2]), "+f"(c[3])
        : "r"(a[0]), "r"(a[1]), "r"(a[2]), "r"(a[3]), "r"(b[0]), "r"(b[1]));
}

#define SMSTRIDE 132
#define GEMM_SMEM (2 * 128 * SMSTRIDE * 4)

__global__ __launch_bounds__(256) void gemm_tc_kernel(
    const float* __restrict__ x,
    const float* __restrict__ src_w, const float* __restrict__ dst_w,
    const float* __restrict__ src_b, const float* __restrict__ dst_b) {
    extern __shared__ float sm[];
    float* As = sm;
    float* Ws = sm + 128 * SMSTRIDE;

    const float* W    = (blockIdx.y == 0) ? src_w : dst_w;
    const float* bias = (blockIdx.y == 0) ? src_b : dst_b;

    int tid = threadIdx.x;
    int rowBase = blockIdx.x * 128;

#pragma unroll
    for (int it = 0; it < 16; it++) {
        int idx = tid + it * 256;
        int r = idx >> 5;
        int c = (idx & 31) * 4;
        float4 v = make_float4(0.f, 0.f, 0.f, 0.f);
        if (rowBase + r < N_NODES)
            v = *(const float4*)&x[(long long)(rowBase + r) * DIM + c];
        *(float4*)&As[r * SMSTRIDE + c] = v;
        float4 wv = *(const float4*)&W[(long long)r * DIM + c];
        *(float4*)&Ws[r * SMSTRIDE + c] = wv;
    }
    __syncthreads();

    int wid = tid >> 5, lane = tid & 31;
    int g = lane >> 2, t = lane & 3;
    int warpM = wid & 3, warpN = wid >> 2;
    int wrow = warpM * 32, wcol = warpN * 64;

    float acc[2][8][4];
#pragma unroll
    for (int mt = 0; mt < 2; mt++)
#pragma unroll
        for (int nt = 0; nt < 8; nt++)
#pragma unroll
            for (int j = 0; j < 4; j++) acc[mt][nt][j] = 0.0f;

    for (int kt = 0; kt < 16; kt++) {
        int k0 = kt * 8;
        uint32_t ahi[2][4], alo[2][4];
#pragma unroll
        for (int mt = 0; mt < 2; mt++) {
            int r0 = wrow + mt * 16;
            float a0 = As[(r0 + g) * SMSTRIDE + k0 + t];
            float a1 = As[(r0 + g + 8) * SMSTRIDE + k0 + t];
            float a2 = As[(r0 + g) * SMSTRIDE + k0 + t + 4];
            float a3 = As[(r0 + g + 8) * SMSTRIDE + k0 + t + 4];
            ahi[mt][0] = f2tf(a0); alo[mt][0] = f2tf(a0 - __uint_as_float(ahi[mt][0]));
            ahi[mt][1] = f2tf(a1); alo[mt][1] = f2tf(a1 - __uint_as_float(ahi[mt][1]));
            ahi[mt][2] = f2tf(a2); alo[mt][2] = f2tf(a2 - __uint_as_float(ahi[mt][2]));
            ahi[mt][3] = f2tf(a3); alo[mt][3] = f2tf(a3 - __uint_as_float(ahi[mt][3]));
        }
        uint32_t bhi[8][2], blo[8][2];
#pragma unroll
        for (int nt = 0; nt < 8; nt++) {
            int col = wcol + nt * 8 + g;
            float b0 = Ws[(k0 + t) * SMSTRIDE + col];
            float b1 = Ws[(k0 + t + 4) * SMSTRIDE + col];
            bhi[nt][0] = f2tf(b0); blo[nt][0] = f2tf(b0 - __uint_as_float(bhi[nt][0]));
            bhi[nt][1] = f2tf(b1); blo[nt][1] = f2tf(b1 - __uint_as_float(bhi[nt][1]));
        }
#pragma unroll
        for (int mt = 0; mt < 2; mt++)
#pragma unroll
            for (int nt = 0; nt < 8; nt++) {
                mma_tf32(acc[mt][nt], ahi[mt], blo[nt]);
                mma_tf32(acc[mt][nt], alo[mt], bhi[nt]);
                mma_tf32(acc[mt][nt], ahi[mt], bhi[nt]);
            }
    }

    bool toComb = (blockIdx.y == 0);
    char* combBase = (char*)g_comb;
#pragma unroll
    for (int mt = 0; mt < 2; mt++) {
#pragma unroll
        for (int nt = 0; nt < 8; nt++) {
            int col = wcol + nt * 8 + 2 * t;
            float b0 = bias[col], b1 = bias[col + 1];
            int row0 = rowBase + wrow + mt * 16 + g;
            int row1 = row0 + 8;
            __half2 h0 = __floats2half2_rn(acc[mt][nt][0] + b0, acc[mt][nt][1] + b1);
            __half2 h1 = __floats2half2_rn(acc[mt][nt][2] + b0, acc[mt][nt][3] + b1);
            if (toComb) {
                // chunk = col>>2 ; byte offset within chunk = 8 + (col&3)*2 (col&3 in {0,2})
                long long off0 = (long long)row0 * 512 + (col >> 2) * 16 + 8 + (col & 3) * 2;
                long long off1 = (long long)row1 * 512 + (col >> 2) * 16 + 8 + (col & 3) * 2;
                if (row0 < N_NODES) *(__half2*)(combBase + off0) = h0;
                if (row1 < N_NODES) *(__half2*)(combBase + off1) = h1;
            } else {
                if (row0 < N_NODES) *(__half2*)&g_xproj[(long long)row0 * DIM + col] = h0;
                if (row1 < N_NODES) *(__half2*)&g_xproj[(long long)row1 * DIM + col] = h1;
            }
        }
    }
}

// ---------------- k5: ha_dst = segment_mean(xproj[src]), warp per dst ------
__device__ __forceinline__ float4 ldh4(const __half* p) {
    uint2 raw = *(const uint2*)p;
    __half2 h0 = *(__half2*)&raw.x;
    __half2 h1 = *(__half2*)&raw.y;
    float2 f0 = __half22float2(h0);
    float2 f1 = __half22float2(h1);
    return make_float4(f0.x, f0.y, f1.x, f1.y);
}

__global__ __launch_bounds__(256) void agg_kernel() {
    int warp = (blockIdx.x * blockDim.x + threadIdx.x) >> 5;
    int lane = threadIdx.x & 31;
    if (warp >= N_NODES) return;
    int beg = g_off[warp];
    int end = g_off[warp + 1];
    float4 acc = make_float4(0.f, 0.f, 0.f, 0.f);
    int p = beg;
    for (; p + 3 < end; p += 4) {
        int s0 = g_ssrc[p], s1 = g_ssrc[p + 1], s2 = g_ssrc[p + 2], s3 = g_ssrc[p + 3];
        float4 v0 = ldh4(&g_xproj[(long long)s0 * DIM + lane * 4]);
        float4 v1 = ldh4(&g_xproj[(long long)s1 * DIM + lane * 4]);
        float4 v2 = ldh4(&g_xproj[(long long)s2 * DIM + lane * 4]);
        float4 v3 = ldh4(&g_xproj[(long long)s3 * DIM + lane * 4]);
        acc.x += v0.x + v1.x + v2.x + v3.x;
        acc.y += v0.y + v1.y + v2.y + v3.y;
        acc.z += v0.z + v1.z + v2.z + v3.z;
        acc.w += v0.w + v1.w + v2.w + v3.w;
    }
    for (; p < end; p++) {
        int s = g_ssrc[p];
        float4 v = ldh4(&g_xproj[(long long)s * DIM + lane * 4]);
        acc.x += v.x; acc.y += v.y; acc.z += v.z; acc.w += v.w;
    }
    float r = 1.0f / (float)max(end - beg, 1);
    float4 o = make_float4(acc.x * r, acc.y * r, acc.z * r, acc.w * r);
    *(float4*)&g_ha_dst[(long long)warp * DIM + lane * 4] = o;
}

// ------- k6: fused score + denom + weighted output (1 LDG.128/edge/lane) ---
__global__ __launch_bounds__(256) void fused_out_kernel(
    const float* __restrict__ att_w,
    const float* __restrict__ att_b,
    float* __restrict__ out) {
    int warp = (blockIdx.x * blockDim.x + threadIdx.x) >> 5;
    int lane = threadIdx.x & 31;
    if (warp >= N_NODES) return;
    int beg = g_off[warp];
    int end = g_off[warp + 1];

    float4 b = *(const float4*)&g_ha_dst[(long long)warp * DIM + lane * 4];
    float4 w = *(const float4*)&att_w[lane * 4];
    float  c = att_b[0];

    float denom = 0.0f;
    float4 o = make_float4(0.f, 0.f, 0.f, 0.f);
    int p = beg;
    for (; p + 1 < end; p += 2) {
        int s0 = g_ssrc[p], s1 = g_ssrc[p + 1];
        uint4 c0 = g_comb[(long long)s0 * 32 + lane];
        uint4 c1 = g_comb[(long long)s1 * 32 + lane];
        float2 x0a = __half22float2(*(__half2*)&c0.x);
        float2 x0b = __half22float2(*(__half2*)&c0.y);
        float2 a0a = __half22float2(*(__half2*)&c0.z);
        float2 a0b = __half22float2(*(__half2*)&c0.w);
        float2 x1a = __half22float2(*(__half2*)&c1.x);
        float2 x1b = __half22float2(*(__half2*)&c1.y);
        float2 a1a = __half22float2(*(__half2*)&c1.z);
        float2 a1b = __half22float2(*(__half2*)&c1.w);
        float t0, t1;
        {
            float v0 = a0a.x + b.x, v1 = a0a.y + b.y, v2 = a0b.x + b.z, v3 = a0b.y + b.w;
            v0 = (v0 >= 0.f) ? v0 : v0 * NEG_SLOPE;
            v1 = (v1 >= 0.f) ? v1 : v1 * NEG_SLOPE;
            v2 = (v2 >= 0.f) ? v2 : v2 * NEG_SLOPE;
            v3 = (v3 >= 0.f) ? v3 : v3 * NEG_SLOPE;
            t0 = v0 * w.x + v1 * w.y + v2 * w.z + v3 * w.w;
        }
        {
            float v0 = a1a.x + b.x, v1 = a1a.y + b.y, v2 = a1b.x + b.z, v3 = a1b.y + b.w;
            v0 = (v0 >= 0.f) ? v0 : v0 * NEG_SLOPE;
            v1 = (v1 >= 0.f) ? v1 : v1 * NEG_SLOPE;
            v2 = (v2 >= 0.f) ? v2 : v2 * NEG_SLOPE;
            v3 = (v3 >= 0.f) ? v3 : v3 * NEG_SLOPE;
            t1 = v0 * w.x + v1 * w.y + v2 * w.z + v3 * w.w;
        }
#pragma unroll
        for (int off = 16; off > 0; off >>= 1) {
            t0 += __shfl_xor_sync(0xFFFFFFFFu, t0, off);
            t1 += __shfl_xor_sync(0xFFFFFFFFu, t1, off);
        }
        float sv0 = expf(t0 + c);
        float sv1 = expf(t1 + c);
        denom += sv0 + sv1;
        o.x += sv0 * x0a.x + sv1 * x1a.x;
        o.y += sv0 * x0a.y + sv1 * x1a.y;
        o.z += sv0 * x0b.x + sv1 * x1b.x;
        o.w += sv0 * x0b.y + sv1 * x1b.y;
    }
    for (; p < end; p++) {
        int s = g_ssrc[p];
        uint4 cc = g_comb[(long long)s * 32 + lane];
        float2 xa = __half22float2(*(__half2*)&cc.x);
        float2 xb = __half22float2(*(__half2*)&cc.y);
        float2 aa = __half22float2(*(__half2*)&cc.z);
        float2 ab = __half22float2(*(__half2*)&cc.w);
        float v0 = aa.x + b.x, v1 = aa.y + b.y, v2 = ab.x + b.z, v3 = ab.y + b.w;
        v0 = (v0 >= 0.f) ? v0 : v0 * NEG_SLOPE;
        v1 = (v1 >= 0.f) ? v1 : v1 * NEG_SLOPE;
        v2 = (v2 >= 0.f) ? v2 : v2 * NEG_SLOPE;
        v3 = (v3 >= 0.f) ? v3 : v3 * NEG_SLOPE;
        float t = v0 * w.x + v1 * w.y + v2 * w.z + v3 * w.w;
#pragma unroll
        for (int off = 16; off > 0; off >>= 1)
            t += __shfl_xor_sync(0xFFFFFFFFu, t, off);
        float sv = expf(t + c);
        denom += sv;
        o.x += sv * xa.x; o.y += sv * xa.y; o.z += sv * xb.x; o.w += sv * xb.y;
    }

    float rd = (end > beg) ? 1.0f / denom : 0.0f;
    float4 r = make_float4(o.x * rd, o.y * rd, o.z * rd, o.w * rd);
    *(float4*)&out[(long long)warp * DIM + lane * 4] = r;
}

// ---------------------------------------------------------------------------
extern "C" void kernel_launch(void* const* d_in, const int* in_sizes, int n_in,
                              void* d_out, int out_size) {
    const float* x       = (const float*)d_in[0];
    const int*   src_idx = (const int*)d_in[1];
    const int*   dst_idx = (const int*)d_in[2];
    const float* src_w   = (const float*)d_in[3];
    const float* src_b   = (const float*)d_in[4];
    const float* dst_w   = (const float*)d_in[5];
    const float* dst_b   = (const float*)d_in[6];
    const float* att_w   = (const float*)d_in[7];
    const float* att_b   = (const float*)d_in[8];
    float* out = (float*)d_out;

    (void)in_sizes; (void)n_in; (void)out_size;

    cudaFuncSetAttribute(gemm_tc_kernel,
                         cudaFuncAttributeMaxDynamicSharedMemorySize, GEMM_SMEM);

    const int e4Blocks = (N_EDGES / 4 + 255) / 256;
    const int nodeWarpBlocks = (N_NODES * 32 + 255) / 256;

    prep_kernel<<<(N_NODES * DIM / 4 + 255) / 256, 256>>>(x);
    hist_kernel<<<e4Blocks, 256>>>(dst_idx);
    scan_a_kernel<<<SCAN_NBLK, SCAN_BLK>>>();
    scan_c_kernel<<<SCAN_NBLK, SCAN_BLK>>>();
    scatter_kernel<<<e4Blocks, 256>>>(src_idx, dst_idx);

    dim3 gemmGrid((N_NODES + 127) / 128, 2);
    gemm_tc_kernel<<<gemmGrid, 256, GEMM_SMEM>>>(x, src_w, dst_w, src_b, dst_b);

    agg_kernel<<<nodeWarpBlocks, 256>>>();

    fused_out_kernel<<<nodeWarpBlocks, 256>>>(att_w, att_b, out);
}

// round 9
// speedup vs baseline: 1.0627x; 1.0487x over previous
#include <cuda_runtime.h>
#include <cuda_bf16.h>
#include <cuda_fp16.h>
#include <cstdint>

#define N_NODES 50000
#define N_EDGES 800000
#define DIM 128
#define NEG_SLOPE 0.01f

#define SCAN_BLK 1024
#define SCAN_NBLK ((N_NODES + SCAN_BLK - 1) / SCAN_BLK)   // 49

// ---------------- scratch (device globals; no allocation allowed) ----------
__device__ int    g_cnt[N_NODES];
__device__ int    g_off[N_NODES + 1];
__device__ int    g_cur[N_NODES];
__device__ int    g_part[64];
__device__ int    g_ssrc[N_EDGES];
// interleaved per-node record: 32 chunks x 16B; chunk c = {x[4c..4c+3] fp16 (8B), ha_src[4c..4c+3] fp16 (8B)}
__device__ uint4  g_comb[N_NODES * 32];
__device__ __half g_xproj[N_NODES * DIM];   // fp16 (x @ dst_w + dst_b)

// ---------------- k0: prep = zero cnt + x->fp16 into comb ------------------
__global__ void prep_kernel(const float* __restrict__ x) {
    int tid = blockIdx.x * blockDim.x + threadIdx.x;
    if (tid < N_NODES) g_cnt[tid] = 0;
    int i = tid * 4;
    if (i < N_NODES * DIM) {
        float4 v = *(const float4*)&x[i];
        __half2 h0 = __floats2half2_rn(v.x, v.y);
        __half2 h1 = __floats2half2_rn(v.z, v.w);
        int row = i >> 7;              // /128
        int chunk = (i & 127) >> 2;    // 0..31
        uint2 u = make_uint2(*(uint32_t*)&h0, *(uint32_t*)&h1);
        *(uint2*)&g_comb[row * 32 + chunk] = u;   // bytes [0:8) of chunk
    }
}

// ---------------- k1: degree histogram over dst (ILP-4) --------------------
__global__ void hist_kernel(const int* __restrict__ dst) {
    int base = (blockIdx.x * blockDim.x + threadIdx.x) * 4;
    if (base + 3 < N_EDGES) {
        int4 d4 = *(const int4*)&dst[base];
        atomicAdd(&g_cnt[d4.x], 1);
        atomicAdd(&g_cnt[d4.y], 1);
        atomicAdd(&g_cnt[d4.z], 1);
        atomicAdd(&g_cnt[d4.w], 1);
    } else {
        for (int e = base; e < N_EDGES; e++) atomicAdd(&g_cnt[dst[e]], 1);
    }
}

// ---------------- k2a: per-block sums --------------------------------------
__global__ __launch_bounds__(SCAN_BLK) void scan_a_kernel() {
    __shared__ int sh[32];
    int tid = threadIdx.x;
    int i = blockIdx.x * SCAN_BLK + tid;
    int v = (i < N_NODES) ? g_cnt[i] : 0;
#pragma unroll
    for (int off = 16; off > 0; off >>= 1) v += __shfl_xor_sync(0xFFFFFFFFu, v, off);
    if ((tid & 31) == 0) sh[tid >> 5] = v;
    __syncthreads();
    if (tid < 32) {
        int s = sh[tid];
#pragma unroll
        for (int off = 16; off > 0; off >>= 1) s += __shfl_xor_sync(0xFFFFFFFFu, s, off);
        if (tid == 0) g_part[blockIdx.x] = s;
    }
}

// ------- k2b: block scan (warp-shuffle) + redundant partial sum -> offsets -
__global__ __launch_bounds__(SCAN_BLK) void scan_c_kernel() {
    __shared__ int warpsum[32];
    __shared__ int blockOff;
    int tid = threadIdx.x;
    int lane = tid & 31, wid = tid >> 5;
    int i = blockIdx.x * SCAN_BLK + tid;
    int v = (i < N_NODES) ? g_cnt[i] : 0;
    int incl = v;
#pragma unroll
    for (int off = 1; off < 32; off <<= 1) {
        int t = __shfl_up_sync(0xFFFFFFFFu, incl, off);
        if (lane >= off) incl += t;
    }
    if (lane == 31) warpsum[wid] = incl;
    if (tid == 0) {
        int s = 0;
        for (int b = 0; b < (int)blockIdx.x; b++) s += g_part[b];
        blockOff = s;
    }
    __syncthreads();
    if (wid == 0) {
        int s = warpsum[lane];
#pragma unroll
        for (int off = 1; off < 32; off <<= 1) {
            int t = __shfl_up_sync(0xFFFFFFFFu, s, off);
            if (lane >= off) s += t;
        }
        warpsum[lane] = s;
    }
    __syncthreads();
    int warpExcl = (wid > 0) ? warpsum[wid - 1] : 0;
    int excl = incl - v + warpExcl + blockOff;
    if (i < N_NODES) {
        g_off[i] = excl;
        g_cur[i] = excl;
    }
    if (i == 0) g_off[N_NODES] = N_EDGES;
}

// ---------------- k3: scatter edges into dst-sorted order (ILP-4) ----------
__global__ void scatter_kernel(const int* __restrict__ src,
                               const int* __restrict__ dst) {
    int base = (blockIdx.x * blockDim.x + threadIdx.x) * 4;
    if (base + 3 < N_EDGES) {
        int4 d4 = *(const int4*)&dst[base];
        int4 s4 = *(const int4*)&src[base];
        int p0 = atomicAdd(&g_cur[d4.x], 1);
        int p1 = atomicAdd(&g_cur[d4.y], 1);
        int p2 = atomicAdd(&g_cur[d4.z], 1);
        int p3 = atomicAdd(&g_cur[d4.w], 1);
        g_ssrc[p0] = s4.x;
        g_ssrc[p1] = s4.y;
        g_ssrc[p2] = s4.z;
        g_ssrc[p3] = s4.w;
    } else {
        for (int e = base; e < N_EDGES; e++) {
            int p = atomicAdd(&g_cur[dst[e]], 1);
            g_ssrc[p] = src[e];
        }
    }
}

// ---------------- tf32x3 tensor-core GEMM (A = x always) -------------------
// y==0: W=src_w -> fp16 into g_comb ha-slots. y==1: W=dst_w -> fp16 g_xproj (with bias).
__device__ __forceinline__ uint32_t f2tf(float f) {
    uint32_t u;
    asm("cvt.rna.tf32.f32 %0, %1;" : "=r"(u) : "f"(f));
    return u;
}

__device__ __forceinline__ void mma_tf32(float* c, const uint32_t* a, const uint32_t* b) {
    asm volatile(
        "mma.sync.aligned.m16n8k8.row.col.f32.tf32.tf32.f32 "
        "{%0,%1,%2,%3}, {%4,%5,%6,%7}, {%8,%9}, {%0,%1,%2,%3};"
        : "+f"(c[0]), "+f"(c[1]), "+f"(c[2]), "+f"(c[3])
        : "r"(a[0]), "r"(a[1]), "r"(a[2]), "r"(a[3]), "r"(b[0]), "r"(b[1]));
}

#define SMSTRIDE 132
#define GEMM_SMEM (2 * 128 * SMSTRIDE * 4)

__global__ __launch_bounds__(256) void gemm_tc_kernel(
    const float* __restrict__ x,
    const float* __restrict__ src_w, const float* __restrict__ dst_w,
    const float* __restrict__ src_b, const float* __restrict__ dst_b) {
    extern __shared__ float sm[];
    float* As = sm;
    float* Ws = sm + 128 * SMSTRIDE;

    const float* W    = (blockIdx.y == 0) ? src_w : dst_w;
    const float* bias = (blockIdx.y == 0) ? src_b : dst_b;

    int tid = threadIdx.x;
    int rowBase = blockIdx.x * 128;

#pragma unroll
    for (int it = 0; it < 16; it++) {
        int idx = tid + it * 256;
        int r = idx >> 5;
        int c = (idx & 31) * 4;
        float4 v = make_float4(0.f, 0.f, 0.f, 0.f);
        if (rowBase + r < N_NODES)
            v = *(const float4*)&x[(long long)(rowBase + r) * DIM + c];
        *(float4*)&As[r * SMSTRIDE + c] = v;
        float4 wv = *(const float4*)&W[(long long)r * DIM + c];
        *(float4*)&Ws[r * SMSTRIDE + c] = wv;
    }
    __syncthreads();

    int wid = tid >> 5, lane = tid & 31;
    int g = lane >> 2, t = lane & 3;
    int warpM = wid & 3, warpN = wid >> 2;
    int wrow = warpM * 32, wcol = warpN * 64;

    float acc[2][8][4];
#pragma unroll
    for (int mt = 0; mt < 2; mt++)
#pragma unroll
        for (int nt = 0; nt < 8; nt++)
#pragma unroll
            for (int j = 0; j < 4; j++) acc[mt][nt][j] = 0.0f;

    for (int kt = 0; kt < 16; kt++) {
        int k0 = kt * 8;
        uint32_t ahi[2][4], alo[2][4];
#pragma unroll
        for (int mt = 0; mt < 2; mt++) {
            int r0 = wrow + mt * 16;
            float a0 = As[(r0 + g) * SMSTRIDE + k0 + t];
            float a1 = As[(r0 + g + 8) * SMSTRIDE + k0 + t];
            float a2 = As[(r0 + g) * SMSTRIDE + k0 + t + 4];
            float a3 = As[(r0 + g + 8) * SMSTRIDE + k0 + t + 4];
            ahi[mt][0] = f2tf(a0); alo[mt][0] = f2tf(a0 - __uint_as_float(ahi[mt][0]));
            ahi[mt][1] = f2tf(a1); alo[mt][1] = f2tf(a1 - __uint_as_float(ahi[mt][1]));
            ahi[mt][2] = f2tf(a2); alo[mt][2] = f2tf(a2 - __uint_as_float(ahi[mt][2]));
            ahi[mt][3] = f2tf(a3); alo[mt][3] = f2tf(a3 - __uint_as_float(ahi[mt][3]));
        }
        uint32_t bhi[8][2], blo[8][2];
#pragma unroll
        for (int nt = 0; nt < 8; nt++) {
            int col = wcol + nt * 8 + g;
            float b0 = Ws[(k0 + t) * SMSTRIDE + col];
            float b1 = Ws[(k0 + t + 4) * SMSTRIDE + col];
            bhi[nt][0] = f2tf(b0); blo[nt][0] = f2tf(b0 - __uint_as_float(bhi[nt][0]));
            bhi[nt][1] = f2tf(b1); blo[nt][1] = f2tf(b1 - __uint_as_float(bhi[nt][1]));
        }
#pragma unroll
        for (int mt = 0; mt < 2; mt++)
#pragma unroll
            for (int nt = 0; nt < 8; nt++) {
                mma_tf32(acc[mt][nt], ahi[mt], blo[nt]);
                mma_tf32(acc[mt][nt], alo[mt], bhi[nt]);
                mma_tf32(acc[mt][nt], ahi[mt], bhi[nt]);
            }
    }

    bool toComb = (blockIdx.y == 0);
    char* combBase = (char*)g_comb;
#pragma unroll
    for (int mt = 0; mt < 2; mt++) {
#pragma unroll
        for (int nt = 0; nt < 8; nt++) {
            int col = wcol + nt * 8 + 2 * t;
            float b0 = bias[col], b1 = bias[col + 1];
            int row0 = rowBase + wrow + mt * 16 + g;
            int row1 = row0 + 8;
            __half2 h0 = __floats2half2_rn(acc[mt][nt][0] + b0, acc[mt][nt][1] + b1);
            __half2 h1 = __floats2half2_rn(acc[mt][nt][2] + b0, acc[mt][nt][3] + b1);
            if (toComb) {
                long long off0 = (long long)row0 * 512 + (col >> 2) * 16 + 8 + (col & 3) * 2;
                long long off1 = (long long)row1 * 512 + (col >> 2) * 16 + 8 + (col & 3) * 2;
                if (row0 < N_NODES) *(__half2*)(combBase + off0) = h0;
                if (row1 < N_NODES) *(__half2*)(combBase + off1) = h1;
            } else {
                if (row0 < N_NODES) *(__half2*)&g_xproj[(long long)row0 * DIM + col] = h0;
                if (row1 < N_NODES) *(__half2*)&g_xproj[(long long)row1 * DIM + col] = h1;
            }
        }
    }
}

// ------- k4: fused mean(xproj) + score + denom + weighted output -----------
// loop 1: b = mean over edges of xproj[src] (== ha_dst row, bias included)
// loop 2: scores from comb records, denom + weighted x accumulation
__global__ __launch_bounds__(256) void fused_out_kernel(
    const float* __restrict__ att_w,
    const float* __restrict__ att_b,
    float* __restrict__ out) {
    int warp = (blockIdx.x * blockDim.x + threadIdx.x) >> 5;
    int lane = threadIdx.x & 31;
    if (warp >= N_NODES) return;
    int beg = g_off[warp];
    int end = g_off[warp + 1];

    // ---- loop 1: ha_dst row in registers ----
    float4 bacc = make_float4(0.f, 0.f, 0.f, 0.f);
    int p = beg;
    for (; p + 3 < end; p += 4) {
        int s0 = g_ssrc[p], s1 = g_ssrc[p + 1], s2 = g_ssrc[p + 2], s3 = g_ssrc[p + 3];
        uint2 r0 = *(const uint2*)&g_xproj[(long long)s0 * DIM + lane * 4];
        uint2 r1 = *(const uint2*)&g_xproj[(long long)s1 * DIM + lane * 4];
        uint2 r2 = *(const uint2*)&g_xproj[(long long)s2 * DIM + lane * 4];
        uint2 r3 = *(const uint2*)&g_xproj[(long long)s3 * DIM + lane * 4];
        float2 f0a = __half22float2(*(__half2*)&r0.x), f0b = __half22float2(*(__half2*)&r0.y);
        float2 f1a = __half22float2(*(__half2*)&r1.x), f1b = __half22float2(*(__half2*)&r1.y);
        float2 f2a = __half22float2(*(__half2*)&r2.x), f2b = __half22float2(*(__half2*)&r2.y);
        float2 f3a = __half22float2(*(__half2*)&r3.x), f3b = __half22float2(*(__half2*)&r3.y);
        bacc.x += f0a.x + f1a.x + f2a.x + f3a.x;
        bacc.y += f0a.y + f1a.y + f2a.y + f3a.y;
        bacc.z += f0b.x + f1b.x + f2b.x + f3b.x;
        bacc.w += f0b.y + f1b.y + f2b.y + f3b.y;
    }
    for (; p < end; p++) {
        int s = g_ssrc[p];
        uint2 r = *(const uint2*)&g_xproj[(long long)s * DIM + lane * 4];
        float2 fa = __half22float2(*(__half2*)&r.x), fb = __half22float2(*(__half2*)&r.y);
        bacc.x += fa.x; bacc.y += fa.y; bacc.z += fb.x; bacc.w += fb.y;
    }
    float rm = 1.0f / (float)max(end - beg, 1);
    float4 b = make_float4(bacc.x * rm, bacc.y * rm, bacc.z * rm, bacc.w * rm);

    float4 w = *(const float4*)&att_w[lane * 4];
    float  c = att_b[0];

    // ---- loop 2: scores + denom + weighted output ----
    float denom = 0.0f;
    float4 o = make_float4(0.f, 0.f, 0.f, 0.f);
    p = beg;
    for (; p + 1 < end; p += 2) {
        int s0 = g_ssrc[p], s1 = g_ssrc[p + 1];
        uint4 c0 = g_comb[(long long)s0 * 32 + lane];
        uint4 c1 = g_comb[(long long)s1 * 32 + lane];
        float2 x0a = __half22float2(*(__half2*)&c0.x);
        float2 x0b = __half22float2(*(__half2*)&c0.y);
        float2 a0a = __half22float2(*(__half2*)&c0.z);
        float2 a0b = __half22float2(*(__half2*)&c0.w);
        float2 x1a = __half22float2(*(__half2*)&c1.x);
        float2 x1b = __half22float2(*(__half2*)&c1.y);
        float2 a1a = __half22float2(*(__half2*)&c1.z);
        float2 a1b = __half22float2(*(__half2*)&c1.w);
        float t0, t1;
        {
            float v0 = a0a.x + b.x, v1 = a0a.y + b.y, v2 = a0b.x + b.z, v3 = a0b.y + b.w;
            v0 = (v0 >= 0.f) ? v0 : v0 * NEG_SLOPE;
            v1 = (v1 >= 0.f) ? v1 : v1 * NEG_SLOPE;
            v2 = (v2 >= 0.f) ? v2 : v2 * NEG_SLOPE;
            v3 = (v3 >= 0.f) ? v3 : v3 * NEG_SLOPE;
            t0 = v0 * w.x + v1 * w.y + v2 * w.z + v3 * w.w;
        }
        {
            float v0 = a1a.x + b.x, v1 = a1a.y + b.y, v2 = a1b.x + b.z, v3 = a1b.y + b.w;
            v0 = (v0 >= 0.f) ? v0 : v0 * NEG_SLOPE;
            v1 = (v1 >= 0.f) ? v1 : v1 * NEG_SLOPE;
            v2 = (v2 >= 0.f) ? v2 : v2 * NEG_SLOPE;
            v3 = (v3 >= 0.f) ? v3 : v3 * NEG_SLOPE;
            t1 = v0 * w.x + v1 * w.y + v2 * w.z + v3 * w.w;
        }
#pragma unroll
        for (int off = 16; off > 0; off >>= 1) {
            t0 += __shfl_xor_sync(0xFFFFFFFFu, t0, off);
            t1 += __shfl_xor_sync(0xFFFFFFFFu, t1, off);
        }
        float sv0 = expf(t0 + c);
        float sv1 = expf(t1 + c);
        denom += sv0 + sv1;
        o.x += sv0 * x0a.x + sv1 * x1a.x;
        o.y += sv0 * x0a.y + sv1 * x1a.y;
        o.z += sv0 * x0b.x + sv1 * x1b.x;
        o.w += sv0 * x0b.y + sv1 * x1b.y;
    }
    for (; p < end; p++) {
        int s = g_ssrc[p];
        uint4 cc = g_comb[(long long)s * 32 + lane];
        float2 xa = __half22float2(*(__half2*)&cc.x);
        float2 xb = __half22float2(*(__half2*)&cc.y);
        float2 aa = __half22float2(*(__half2*)&cc.z);
        float2 ab = __half22float2(*(__half2*)&cc.w);
        float v0 = aa.x + b.x, v1 = aa.y + b.y, v2 = ab.x + b.z, v3 = ab.y + b.w;
        v0 = (v0 >= 0.f) ? v0 : v0 * NEG_SLOPE;
        v1 = (v1 >= 0.f) ? v1 : v1 * NEG_SLOPE;
        v2 = (v2 >= 0.f) ? v2 : v2 * NEG_SLOPE;
        v3 = (v3 >= 0.f) ? v3 : v3 * NEG_SLOPE;
        float t = v0 * w.x + v1 * w.y + v2 * w.z + v3 * w.w;
#pragma unroll
        for (int off = 16; off > 0; off >>= 1)
            t += __shfl_xor_sync(0xFFFFFFFFu, t, off);
        float sv = expf(t + c);
        denom += sv;
        o.x += sv * xa.x; o.y += sv * xa.y; o.z += sv * xb.x; o.w += sv * xb.y;
    }

    float rd = (end > beg) ? 1.0f / denom : 0.0f;
    float4 r = make_float4(o.x * rd, o.y * rd, o.z * rd, o.w * rd);
    *(float4*)&out[(long long)warp * DIM + lane * 4] = r;
}

// ---------------------------------------------------------------------------
extern "C" void kernel_launch(void* const* d_in, const int* in_sizes, int n_in,
                              void* d_out, int out_size) {
    const float* x       = (const float*)d_in[0];
    const int*   src_idx = (const int*)d_in[1];
    const int*   dst_idx = (const int*)d_in[2];
    const float* src_w   = (const float*)d_in[3];
    const float* src_b   = (const float*)d_in[4];
    const float* dst_w   = (const float*)d_in[5];
    const float* dst_b   = (const float*)d_in[6];
    const float* att_w   = (const float*)d_in[7];
    const float* att_b   = (const float*)d_in[8];
    float* out = (float*)d_out;

    (void)in_sizes; (void)n_in; (void)out_size;

    static cudaStream_t s2 = nullptr;
    static cudaEvent_t evFork = nullptr, evJoin = nullptr;
    if (s2 == nullptr) {
        cudaStreamCreateWithFlags(&s2, cudaStreamNonBlocking);
        cudaEventCreateWithFlags(&evFork, cudaEventDisableTiming);
        cudaEventCreateWithFlags(&evJoin, cudaEventDisableTiming);
        cudaFuncSetAttribute(gemm_tc_kernel,
                             cudaFuncAttributeMaxDynamicSharedMemorySize, GEMM_SMEM);
    }

    const int e4Blocks = (N_EDGES / 4 + 255) / 256;
    const int nodeWarpBlocks = (N_NODES * 32 + 255) / 256;

    // fork: GEMM branch (depends only on x + weights)
    cudaEventRecord(evFork, 0);
    cudaStreamWaitEvent(s2, evFork, 0);
    dim3 gemmGrid((N_NODES + 127) / 128, 2);
    gemm_tc_kernel<<<gemmGrid, 256, GEMM_SMEM, s2>>>(x, src_w, dst_w, src_b, dst_b);
    cudaEventRecord(evJoin, s2);

    // main branch: CSR build
    prep_kernel<<<(N_NODES * DIM / 4 + 255) / 256, 256>>>(x);
    hist_kernel<<<e4Blocks, 256>>>(dst_idx);
    scan_a_kernel<<<SCAN_NBLK, SCAN_BLK>>>();
    scan_c_kernel<<<SCAN_NBLK, SCAN_BLK>>>();
    scatter_kernel<<<e4Blocks, 256>>>(src_idx, dst_idx);

    // join: fused needs comb (prep + gemm y0), xproj (gemm y1), CSR
    cudaStreamWaitEvent(0, evJoin, 0);
    fused_out_kernel<<<nodeWarpBlocks, 256>>>(att_w, att_b, out);
}

// round 10
// speedup vs baseline: 1.0647x; 1.0019x over previous
#include <cuda_runtime.h>
#include <cuda_bf16.h>
#include <cuda_fp16.h>
#include <cstdint>

#define N_NODES 50000
#define N_EDGES 800000
#define DIM 128
#define NEG_SLOPE 0.01f

#define CSR_BLOCKS 592          // 148 SMs * 4 blocks; all resident (256 thr, low regs)
#define CSR_THREADS 256
#define TILE 1024
#define NT ((N_NODES + TILE - 1) / TILE)   // 49

// ---------------- scratch (device globals; no allocation allowed) ----------
__device__ int    g_cnt[N_NODES];          // self-restoring: zeroed by scan phase
__device__ int    g_off[N_NODES + 1];
__device__ int    g_cur[N_NODES];
__device__ int    g_part[64];
__device__ int    g_ssrc[N_EDGES];
// interleaved per-node record: 32 chunks x 16B; chunk c = {x[4c..4c+3] fp16, ha_src[4c..4c+3] fp16}
__device__ uint4  g_comb[N_NODES * 32];
__device__ __half g_xproj[N_NODES * DIM];  // fp16 (x @ dst_w + dst_b)
__device__ int    g_bar_count;
__device__ int    g_bar_gen;

// ---------------- software grid barrier (all blocks resident) --------------
__device__ __forceinline__ void grid_barrier() {
    __syncthreads();
    if (threadIdx.x == 0) {
        int gen = *(volatile int*)&g_bar_gen;
        __threadfence();
        int arrived = atomicAdd(&g_bar_count, 1);
        if (arrived == (int)gridDim.x - 1) {
            g_bar_count = 0;
            __threadfence();
            *(volatile int*)&g_bar_gen = gen + 1;
        } else {
            while (*(volatile int*)&g_bar_gen == gen) __nanosleep(100);
        }
        __threadfence();
    }
    __syncthreads();
}

// ---------------- k1: persistent CSR build (hist -> scan -> scatter) -------
__global__ __launch_bounds__(CSR_THREADS) void csr_kernel(
    const int* __restrict__ src, const int* __restrict__ dst) {
    int tid = threadIdx.x;
    int gthread = blockIdx.x * CSR_THREADS + tid;
    const int gstride = CSR_BLOCKS * CSR_THREADS;

    // ---- phase 1: histogram (g_cnt must be all-zero on entry: invariant) --
    for (int slot = gthread; slot < N_EDGES / 4; slot += gstride) {
        int4 d4 = *(const int4*)&dst[slot * 4];
        atomicAdd(&g_cnt[d4.x], 1);
        atomicAdd(&g_cnt[d4.y], 1);
        atomicAdd(&g_cnt[d4.z], 1);
        atomicAdd(&g_cnt[d4.w], 1);
    }
    grid_barrier();

    // ---- phase 2a: tile sums (blocks 0..NT-1) ----
    __shared__ int sh[64];
    __shared__ int warpsum[8];
    if (blockIdx.x < NT) {
        int base = blockIdx.x * TILE;
        int idx = base + tid * 4;
        int s = 0;
#pragma unroll
        for (int k = 0; k < 4; k++)
            if (idx + k < N_NODES) s += g_cnt[idx + k];
#pragma unroll
        for (int off = 16; off > 0; off >>= 1)
            s += __shfl_xor_sync(0xFFFFFFFFu, s, off);
        if ((tid & 31) == 0) warpsum[tid >> 5] = s;
        __syncthreads();
        if (tid < 8) {
            int t = warpsum[tid];
#pragma unroll
            for (int off = 4; off > 0; off >>= 1)
                t += __shfl_xor_sync(0xFFu, t, off);
            if (tid == 0) g_part[blockIdx.x] = t;
        }
    }
    grid_barrier();

    // ---- phase 2b: exclusive scan of NT tile sums (block 0) ----
    if (blockIdx.x == 0) {
        int v = 0;
        if (tid < 64) {
            v = (tid < NT) ? g_part[tid] : 0;
            sh[tid] = v;
        }
        __syncthreads();
        for (int off = 1; off < 64; off <<= 1) {
            int t = 0;
            if (tid < 64 && tid >= off) t = sh[tid - off];
            __syncthreads();
            if (tid < 64) sh[tid] += t;
            __syncthreads();
        }
        if (tid < NT) g_part[tid] = sh[tid] - v;   // exclusive
    }
    grid_barrier();

    // ---- phase 2c: local exclusive scan + offsets; zero g_cnt (restore) ---
    if (blockIdx.x < NT) {
        int base = blockIdx.x * TILE;
        int idx = base + tid * 4;
        int c0 = 0, c1 = 0, c2 = 0, c3 = 0;
        if (idx + 0 < N_NODES) c0 = g_cnt[idx + 0];
        if (idx + 1 < N_NODES) c1 = g_cnt[idx + 1];
        if (idx + 2 < N_NODES) c2 = g_cnt[idx + 2];
        if (idx + 3 < N_NODES) c3 = g_cnt[idx + 3];
        int mysum = c0 + c1 + c2 + c3;
        int lane = tid & 31, wid = tid >> 5;
        int incl = mysum;
#pragma unroll
        for (int off = 1; off < 32; off <<= 1) {
            int t = __shfl_up_sync(0xFFFFFFFFu, incl, off);
            if (lane >= off) incl += t;
        }
        if (lane == 31) warpsum[wid] = incl;
        __syncthreads();
        if (wid == 0) {
            int s = (lane < 8) ? warpsum[lane] : 0;
#pragma unroll
            for (int off = 1; off < 8; off <<= 1) {
                int t = __shfl_up_sync(0xFFFFFFFFu, s, off);
                if (lane >= off) s += t;
            }
            if (lane < 8) warpsum[lane] = s;
        }
        __syncthreads();
        int warpExcl = (wid > 0) ? warpsum[wid - 1] : 0;
        int excl = incl - mysum + warpExcl + g_part[blockIdx.x];
        int o0 = excl, o1 = o0 + c0, o2 = o1 + c1, o3 = o2 + c2;
        if (idx + 0 < N_NODES) { g_off[idx + 0] = o0; g_cur[idx + 0] = o0; g_cnt[idx + 0] = 0; }
        if (idx + 1 < N_NODES) { g_off[idx + 1] = o1; g_cur[idx + 1] = o1; g_cnt[idx + 1] = 0; }
        if (idx + 2 < N_NODES) { g_off[idx + 2] = o2; g_cur[idx + 2] = o2; g_cnt[idx + 2] = 0; }
        if (idx + 3 < N_NODES) { g_off[idx + 3] = o3; g_cur[idx + 3] = o3; g_cnt[idx + 3] = 0; }
        if (blockIdx.x == 0 && tid == 0) g_off[N_NODES] = N_EDGES;
    }
    grid_barrier();

    // ---- phase 3: scatter ----
    for (int slot = gthread; slot < N_EDGES / 4; slot += gstride) {
        int4 d4 = *(const int4*)&dst[slot * 4];
        int4 s4 = *(const int4*)&src[slot * 4];
        int p0 = atomicAdd(&g_cur[d4.x], 1);
        int p1 = atomicAdd(&g_cur[d4.y], 1);
        int p2 = atomicAdd(&g_cur[d4.z], 1);
        int p3 = atomicAdd(&g_cur[d4.w], 1);
        g_ssrc[p0] = s4.x;
        g_ssrc[p1] = s4.y;
        g_ssrc[p2] = s4.z;
        g_ssrc[p3] = s4.w;
    }
}

// ---------------- tf32x3 tensor-core GEMM (A = x always) -------------------
// y==0: W=src_w -> fp16 into g_comb ha-slots (+ x fp16 into comb x-slots during staging).
// y==1: W=dst_w -> fp16 g_xproj (with bias).
__device__ __forceinline__ uint32_t f2tf(float f) {
    uint32_t u;
    asm("cvt.rna.tf32.f32 %0, %1;" : "=r"(u) : "f"(f));
    return u;
}

__device__ __forceinline__ void mma_tf32(float* c, const uint32_t* a, const uint32_t* b) {
    asm volatile(
        "mma.sync.aligned.m16n8k8.row.col.f32.tf32.tf32.f32 "
        "{%0,%1,%2,%3}, {%4,%5,%6,%7}, {%8,%9}, {%0,%1,%2,%3};"
        : "+f"(c[0]), "+f"(c[1]), "+f"(c[2]), "+f"(c[3])
        : "r"(a[0]), "r"(a[1]), "r"(a[2]), "r"(a[3]), "r"(b[0]), "r"(b[1]));
}

#define SMSTRIDE 132
#define GEMM_SMEM (2 * 128 * SMSTRIDE * 4)

__global__ __launch_bounds__(256) void gemm_tc_kernel(
    const float* __restrict__ x,
    const float* __restrict__ src_w, const float* __restrict__ dst_w,
    const float* __restrict__ src_b, const float* __restrict__ dst_b) {
    extern __shared__ float sm[];
    float* As = sm;
    float* Ws = sm + 128 * SMSTRIDE;

    const float* W    = (blockIdx.y == 0) ? src_w : dst_w;
    const float* bias = (blockIdx.y == 0) ? src_b : dst_b;

    int tid = threadIdx.x;
    int rowBase = blockIdx.x * 128;
    char* combBase = (char*)g_comb;

#pragma unroll
    for (int it = 0; it < 16; it++) {
        int idx = tid + it * 256;
        int r = idx >> 5;
        int c = (idx & 31) * 4;
        float4 v = make_float4(0.f, 0.f, 0.f, 0.f);
        bool inb = (rowBase + r < N_NODES);
        if (inb)
            v = *(const float4*)&x[(long long)(rowBase + r) * DIM + c];
        *(float4*)&As[r * SMSTRIDE + c] = v;
        if (blockIdx.y == 0 && inb) {
            // write x fp16 into comb chunk bytes [0:8)
            __half2 h0 = __floats2half2_rn(v.x, v.y);
            __half2 h1 = __floats2half2_rn(v.z, v.w);
            uint2 u = make_uint2(*(uint32_t*)&h0, *(uint32_t*)&h1);
            *(uint2*)(combBase + (long long)(rowBase + r) * 512 + (c >> 2) * 16) = u;
        }
        float4 wv = *(const float4*)&W[(long long)r * DIM + c];
        *(float4*)&Ws[r * SMSTRIDE + c] = wv;
    }
    __syncthreads();

    int wid = tid >> 5, lane = tid & 31;
    int g = lane >> 2, t = lane & 3;
    int warpM = wid & 3, warpN = wid >> 2;
    int wrow = warpM * 32, wcol = warpN * 64;

    float acc[2][8][4];
#pragma unroll
    for (int mt = 0; mt < 2; mt++)
#pragma unroll
        for (int nt = 0; nt < 8; nt++)
#pragma unroll
            for (int j = 0; j < 4; j++) acc[mt][nt][j] = 0.0f;

    for (int kt = 0; kt < 16; kt++) {
        int k0 = kt * 8;
        uint32_t ahi[2][4], alo[2][4];
#pragma unroll
        for (int mt = 0; mt < 2; mt++) {
            int r0 = wrow + mt * 16;
            float a0 = As[(r0 + g) * SMSTRIDE + k0 + t];
            float a1 = As[(r0 + g + 8) * SMSTRIDE + k0 + t];
            float a2 = As[(r0 + g) * SMSTRIDE + k0 + t + 4];
            float a3 = As[(r0 + g + 8) * SMSTRIDE + k0 + t + 4];
            ahi[mt][0] = f2tf(a0); alo[mt][0] = f2tf(a0 - __uint_as_float(ahi[mt][0]));
            ahi[mt][1] = f2tf(a1); alo[mt][1] = f2tf(a1 - __uint_as_float(ahi[mt][1]));
            ahi[mt][2] = f2tf(a2); alo[mt][2] = f2tf(a2 - __uint_as_float(ahi[mt][2]));
            ahi[mt][3] = f2tf(a3); alo[mt][3] = f2tf(a3 - __uint_as_float(ahi[mt][3]));
        }
        uint32_t bhi[8][2], blo[8][2];
#pragma unroll
        for (int nt = 0; nt < 8; nt++) {
            int col = wcol + nt * 8 + g;
            float b0 = Ws[(k0 + t) * SMSTRIDE + col];
            float b1 = Ws[(k0 + t + 4) * SMSTRIDE + col];
            bhi[nt][0] = f2tf(b0); blo[nt][0] = f2tf(b0 - __uint_as_float(bhi[nt][0]));
            bhi[nt][1] = f2tf(b1); blo[nt][1] = f2tf(b1 - __uint_as_float(bhi[nt][1]));
        }
#pragma unroll
        for (int mt = 0; mt < 2; mt++)
#pragma unroll
            for (int nt = 0; nt < 8; nt++) {
                mma_tf32(acc[mt][nt], ahi[mt], blo[nt]);
                mma_tf32(acc[mt][nt], alo[mt], bhi[nt]);
                mma_tf32(acc[mt][nt], ahi[mt], bhi[nt]);
            }
    }

    bool toComb = (blockIdx.y == 0);
#pragma unroll
    for (int mt = 0; mt < 2; mt++) {
#pragma unroll
        for (int nt = 0; nt < 8; nt++) {
            int col = wcol + nt * 8 + 2 * t;
            float b0 = bias[col], b1 = bias[col + 1];
            int row0 = rowBase + wrow + mt * 16 + g;
            int row1 = row0 + 8;
            __half2 h0 = __floats2half2_rn(acc[mt][nt][0] + b0, acc[mt][nt][1] + b1);
            __half2 h1 = __floats2half2_rn(acc[mt][nt][2] + b0, acc[mt][nt][3] + b1);
            if (toComb) {
                long long off0 = (long long)row0 * 512 + (col >> 2) * 16 + 8 + (col & 3) * 2;
                long long off1 = (long long)row1 * 512 + (col >> 2) * 16 + 8 + (col & 3) * 2;
                if (row0 < N_NODES) *(__half2*)((char*)g_comb + off0) = h0;
                if (row1 < N_NODES) *(__half2*)((char*)g_comb + off1) = h1;
            } else {
                if (row0 < N_NODES) *(__half2*)&g_xproj[(long long)row0 * DIM + col] = h0;
                if (row1 < N_NODES) *(__half2*)&g_xproj[(long long)row1 * DIM + col] = h1;
            }
        }
    }
}

// ------- k3: fused mean(xproj) + score + denom + weighted output -----------
__global__ __launch_bounds__(256) void fused_out_kernel(
    const float* __restrict__ att_w,
    const float* __restrict__ att_b,
    float* __restrict__ out) {
    int warp = (blockIdx.x * blockDim.x + threadIdx.x) >> 5;
    int lane = threadIdx.x & 31;
    if (warp >= N_NODES) return;
    int beg = g_off[warp];
    int end = g_off[warp + 1];

    // ---- loop 1: ha_dst row (mean of xproj[src]) in registers ----
    float4 bacc = make_float4(0.f, 0.f, 0.f, 0.f);
    int p = beg;
    for (; p + 3 < end; p += 4) {
        int s0 = g_ssrc[p], s1 = g_ssrc[p + 1], s2 = g_ssrc[p + 2], s3 = g_ssrc[p + 3];
        uint2 r0 = *(const uint2*)&g_xproj[(long long)s0 * DIM + lane * 4];
        uint2 r1 = *(const uint2*)&g_xproj[(long long)s1 * DIM + lane * 4];
        uint2 r2 = *(const uint2*)&g_xproj[(long long)s2 * DIM + lane * 4];
        uint2 r3 = *(const uint2*)&g_xproj[(long long)s3 * DIM + lane * 4];
        float2 f0a = __half22float2(*(__half2*)&r0.x), f0b = __half22float2(*(__half2*)&r0.y);
        float2 f1a = __half22float2(*(__half2*)&r1.x), f1b = __half22float2(*(__half2*)&r1.y);
        float2 f2a = __half22float2(*(__half2*)&r2.x), f2b = __half22float2(*(__half2*)&r2.y);
        float2 f3a = __half22float2(*(__half2*)&r3.x), f3b = __half22float2(*(__half2*)&r3.y);
        bacc.x += f0a.x + f1a.x + f2a.x + f3a.x;
        bacc.y += f0a.y + f1a.y + f2a.y + f3a.y;
        bacc.z += f0b.x + f1b.x + f2b.x + f3b.x;
        bacc.w += f0b.y + f1b.y + f2b.y + f3b.y;
    }
    for (; p < end; p++) {
        int s = g_ssrc[p];
        uint2 r = *(const uint2*)&g_xproj[(long long)s * DIM + lane * 4];
        float2 fa = __half22float2(*(__half2*)&r.x), fb = __half22float2(*(__half2*)&r.y);
        bacc.x += fa.x; bacc.y += fa.y; bacc.z += fb.x; bacc.w += fb.y;
    }
    float rm = 1.0f / (float)max(end - beg, 1);
    float4 b = make_float4(bacc.x * rm, bacc.y * rm, bacc.z * rm, bacc.w * rm);

    float4 w = *(const float4*)&att_w[lane * 4];
    float  c = att_b[0];

    // ---- loop 2: scores + denom + weighted output ----
    float denom = 0.0f;
    float4 o = make_float4(0.f, 0.f, 0.f, 0.f);
    p = beg;
    for (; p + 1 < end; p += 2) {
        int s0 = g_ssrc[p], s1 = g_ssrc[p + 1];
        uint4 c0 = g_comb[(long long)s0 * 32 + lane];
        uint4 c1 = g_comb[(long long)s1 * 32 + lane];
        float2 x0a = __half22float2(*(__half2*)&c0.x);
        float2 x0b = __half22float2(*(__half2*)&c0.y);
        float2 a0a = __half22float2(*(__half2*)&c0.z);
        float2 a0b = __half22float2(*(__half2*)&c0.w);
        float2 x1a = __half22float2(*(__half2*)&c1.x);
        float2 x1b = __half22float2(*(__half2*)&c1.y);
        float2 a1a = __half22float2(*(__half2*)&c1.z);
        float2 a1b = __half22float2(*(__half2*)&c1.w);
        float t0, t1;
        {
            float v0 = a0a.x + b.x, v1 = a0a.y + b.y, v2 = a0b.x + b.z, v3 = a0b.y + b.w;
            v0 = (v0 >= 0.f) ? v0 : v0 * NEG_SLOPE;
            v1 = (v1 >= 0.f) ? v1 : v1 * NEG_SLOPE;
            v2 = (v2 >= 0.f) ? v2 : v2 * NEG_SLOPE;
            v3 = (v3 >= 0.f) ? v3 : v3 * NEG_SLOPE;
            t0 = v0 * w.x + v1 * w.y + v2 * w.z + v3 * w.w;
        }
        {
            float v0 = a1a.x + b.x, v1 = a1a.y + b.y, v2 = a1b.x + b.z, v3 = a1b.y + b.w;
            v0 = (v0 >= 0.f) ? v0 : v0 * NEG_SLOPE;
            v1 = (v1 >= 0.f) ? v1 : v1 * NEG_SLOPE;
            v2 = (v2 >= 0.f) ? v2 : v2 * NEG_SLOPE;
            v3 = (v3 >= 0.f) ? v3 : v3 * NEG_SLOPE;
            t1 = v0 * w.x + v1 * w.y + v2 * w.z + v3 * w.w;
        }
#pragma unroll
        for (int off = 16; off > 0; off >>= 1) {
            t0 += __shfl_xor_sync(0xFFFFFFFFu, t0, off);
            t1 += __shfl_xor_sync(0xFFFFFFFFu, t1, off);
        }
        float sv0 = expf(t0 + c);
        float sv1 = expf(t1 + c);
        denom += sv0 + sv1;
        o.x += sv0 * x0a.x + sv1 * x1a.x;
        o.y += sv0 * x0a.y + sv1 * x1a.y;
        o.z += sv0 * x0b.x + sv1 * x1b.x;
        o.w += sv0 * x0b.y + sv1 * x1b.y;
    }
    for (; p < end; p++) {
        int s = g_ssrc[p];
        uint4 cc = g_comb[(long long)s * 32 + lane];
        float2 xa = __half22float2(*(__half2*)&cc.x);
        float2 xb = __half22float2(*(__half2*)&cc.y);
        float2 aa = __half22float2(*(__half2*)&cc.z);
        float2 ab = __half22float2(*(__half2*)&cc.w);
        float v0 = aa.x + b.x, v1 = aa.y + b.y, v2 = ab.x + b.z, v3 = ab.y + b.w;
        v0 = (v0 >= 0.f) ? v0 : v0 * NEG_SLOPE;
        v1 = (v1 >= 0.f) ? v1 : v1 * NEG_SLOPE;
        v2 = (v2 >= 0.f) ? v2 : v2 * NEG_SLOPE;
        v3 = (v3 >= 0.f) ? v3 : v3 * NEG_SLOPE;
        float t = v0 * w.x + v1 * w.y + v2 * w.z + v3 * w.w;
#pragma unroll
        for (int off = 16; off > 0; off >>= 1)
            t += __shfl_xor_sync(0xFFFFFFFFu, t, off);
        float sv = expf(t + c);
        denom += sv;
        o.x += sv * xa.x; o.y += sv * xa.y; o.z += sv * xb.x; o.w += sv * xb.y;
    }

    float rd = (end > beg) ? 1.0f / denom : 0.0f;
    float4 r = make_float4(o.x * rd, o.y * rd, o.z * rd, o.w * rd);
    *(float4*)&out[(long long)warp * DIM + lane * 4] = r;
}

// ---------------------------------------------------------------------------
extern "C" void kernel_launch(void* const* d_in, const int* in_sizes, int n_in,
                              void* d_out, int out_size) {
    const float* x       = (const float*)d_in[0];
    const int*   src_idx = (const int*)d_in[1];
    const int*   dst_idx = (const int*)d_in[2];
    const float* src_w   = (const float*)d_in[3];
    const float* src_b   = (const float*)d_in[4];
    const float* dst_w   = (const float*)d_in[5];
    const float* dst_b   = (const float*)d_in[6];
    const float* att_w   = (const float*)d_in[7];
    const float* att_b   = (const float*)d_in[8];
    float* out = (float*)d_out;

    (void)in_sizes; (void)n_in; (void)out_size;

    static cudaStream_t s2 = nullptr;
    static cudaEvent_t evFork = nullptr, evJoin = nullptr;
    if (s2 == nullptr) {
        cudaStreamCreateWithFlags(&s2, cudaStreamNonBlocking);
        cudaEventCreateWithFlags(&evFork, cudaEventDisableTiming);
        cudaEventCreateWithFlags(&evJoin, cudaEventDisableTiming);
        cudaFuncSetAttribute(gemm_tc_kernel,
                             cudaFuncAttributeMaxDynamicSharedMemorySize, GEMM_SMEM);
    }

    const int nodeWarpBlocks = (N_NODES * 32 + 255) / 256;

    // fork: GEMM branch (x + weights only; also produces comb x-halves)
    cudaEventRecord(evFork, 0);
    cudaStreamWaitEvent(s2, evFork, 0);
    dim3 gemmGrid((N_NODES + 127) / 128, 2);
    gemm_tc_kernel<<<gemmGrid, 256, GEMM_SMEM, s2>>>(x, src_w, dst_w, src_b, dst_b);
    cudaEventRecord(evJoin, s2);

    // main branch: one persistent CSR build kernel
    csr_kernel<<<CSR_BLOCKS, CSR_THREADS>>>(src_idx, dst_idx);

    // join
    cudaStreamWaitEvent(0, evJoin, 0);
    fused_out_kernel<<<nodeWarpBlocks, 256>>>(att_w, att_b, out);
}

// round 11
// speedup vs baseline: 1.2703x; 1.1932x over previous
#include <cuda_runtime.h>
#include <cuda_bf16.h>
#include <cuda_fp16.h>
#include <cstdint>

#define N_NODES 50000
#define N_EDGES 800000
#define DIM 128
#define NEG_SLOPE 0.01f

#define CSR_BLOCKS 592
#define CSR_THREADS 256
#define TILE 1024
#define NT ((N_NODES + TILE - 1) / TILE)   // 49

// ---------------- scratch (device globals; no allocation allowed) ----------
__device__ int    g_cnt[N_NODES];          // self-restoring: zeroed by scan phase
__device__ int    g_off[N_NODES + 1];
__device__ int    g_cur[N_NODES];
__device__ int    g_part[64];
__device__ int    g_ssrc[N_EDGES];
// interleaved per-node record: 32 chunks x 16B; chunk c = {x[4c..4c+3] fp16, ha_src[4c..4c+3] fp16}
__device__ uint4  g_comb[N_NODES * 32];
__device__ __half g_xproj[N_NODES * DIM];  // fp16 (x @ dst_w + dst_b)
__device__ int    g_bar_count;
__device__ int    g_bar_gen;

// ---------------- software grid barrier (all blocks resident) --------------
__device__ __forceinline__ void grid_barrier() {
    __syncthreads();
    if (threadIdx.x == 0) {
        int gen = *(volatile int*)&g_bar_gen;
        __threadfence();
        int arrived = atomicAdd(&g_bar_count, 1);
        if (arrived == (int)gridDim.x - 1) {
            g_bar_count = 0;
            __threadfence();
            *(volatile int*)&g_bar_gen = gen + 1;
        } else {
            while (*(volatile int*)&g_bar_gen == gen) __nanosleep(100);
        }
        __threadfence();
    }
    __syncthreads();
}

// ---------------- k1: persistent CSR build (hist -> scan -> scatter) -------
__global__ __launch_bounds__(CSR_THREADS) void csr_kernel(
    const int* __restrict__ src, const int* __restrict__ dst) {
    int tid = threadIdx.x;
    int gthread = blockIdx.x * CSR_THREADS + tid;
    const int gstride = CSR_BLOCKS * CSR_THREADS;

    // ---- phase 1: histogram ----
    for (int slot = gthread; slot < N_EDGES / 4; slot += gstride) {
        int4 d4 = *(const int4*)&dst[slot * 4];
        atomicAdd(&g_cnt[d4.x], 1);
        atomicAdd(&g_cnt[d4.y], 1);
        atomicAdd(&g_cnt[d4.z], 1);
        atomicAdd(&g_cnt[d4.w], 1);
    }
    grid_barrier();

    // ---- phase 2a: tile sums ----
    __shared__ int sh[64];
    __shared__ int warpsum[8];
    if (blockIdx.x < NT) {
        int base = blockIdx.x * TILE;
        int idx = base + tid * 4;
        int s = 0;
#pragma unroll
        for (int k = 0; k < 4; k++)
            if (idx + k < N_NODES) s += g_cnt[idx + k];
#pragma unroll
        for (int off = 16; off > 0; off >>= 1)
            s += __shfl_xor_sync(0xFFFFFFFFu, s, off);
        if ((tid & 31) == 0) warpsum[tid >> 5] = s;
        __syncthreads();
        if (tid < 8) {
            int t = warpsum[tid];
#pragma unroll
            for (int off = 4; off > 0; off >>= 1)
                t += __shfl_xor_sync(0xFFu, t, off);
            if (tid == 0) g_part[blockIdx.x] = t;
        }
    }
    grid_barrier();

    // ---- phase 2b: exclusive scan of NT tile sums ----
    if (blockIdx.x == 0) {
        int v = 0;
        if (tid < 64) {
            v = (tid < NT) ? g_part[tid] : 0;
            sh[tid] = v;
        }
        __syncthreads();
        for (int off = 1; off < 64; off <<= 1) {
            int t = 0;
            if (tid < 64 && tid >= off) t = sh[tid - off];
            __syncthreads();
            if (tid < 64) sh[tid] += t;
            __syncthreads();
        }
        if (tid < NT) g_part[tid] = sh[tid] - v;
    }
    grid_barrier();

    // ---- phase 2c: local scan + offsets; zero g_cnt ----
    if (blockIdx.x < NT) {
        int base = blockIdx.x * TILE;
        int idx = base + tid * 4;
        int c0 = 0, c1 = 0, c2 = 0, c3 = 0;
        if (idx + 0 < N_NODES) c0 = g_cnt[idx + 0];
        if (idx + 1 < N_NODES) c1 = g_cnt[idx + 1];
        if (idx + 2 < N_NODES) c2 = g_cnt[idx + 2];
        if (idx + 3 < N_NODES) c3 = g_cnt[idx + 3];
        int mysum = c0 + c1 + c2 + c3;
        int lane = tid & 31, wid = tid >> 5;
        int incl = mysum;
#pragma unroll
        for (int off = 1; off < 32; off <<= 1) {
            int t = __shfl_up_sync(0xFFFFFFFFu, incl, off);
            if (lane >= off) incl += t;
        }
        if (lane == 31) warpsum[wid] = incl;
        __syncthreads();
        if (wid == 0) {
            int s = (lane < 8) ? warpsum[lane] : 0;
#pragma unroll
            for (int off = 1; off < 8; off <<= 1) {
                int t = __shfl_up_sync(0xFFFFFFFFu, s, off);
                if (lane >= off) s += t;
            }
            if (lane < 8) warpsum[lane] = s;
        }
        __syncthreads();
        int warpExcl = (wid > 0) ? warpsum[wid - 1] : 0;
        int excl = incl - mysum + warpExcl + g_part[blockIdx.x];
        int o0 = excl, o1 = o0 + c0, o2 = o1 + c1, o3 = o2 + c2;
        if (idx + 0 < N_NODES) { g_off[idx + 0] = o0; g_cur[idx + 0] = o0; g_cnt[idx + 0] = 0; }
        if (idx + 1 < N_NODES) { g_off[idx + 1] = o1; g_cur[idx + 1] = o1; g_cnt[idx + 1] = 0; }
        if (idx + 2 < N_NODES) { g_off[idx + 2] = o2; g_cur[idx + 2] = o2; g_cnt[idx + 2] = 0; }
        if (idx + 3 < N_NODES) { g_off[idx + 3] = o3; g_cur[idx + 3] = o3; g_cnt[idx + 3] = 0; }
        if (blockIdx.x == 0 && tid == 0) g_off[N_NODES] = N_EDGES;
    }
    grid_barrier();

    // ---- phase 3: scatter ----
    for (int slot = gthread; slot < N_EDGES / 4; slot += gstride) {
        int4 d4 = *(const int4*)&dst[slot * 4];
        int4 s4 = *(const int4*)&src[slot * 4];
        int p0 = atomicAdd(&g_cur[d4.x], 1);
        int p1 = atomicAdd(&g_cur[d4.y], 1);
        int p2 = atomicAdd(&g_cur[d4.z], 1);
        int p3 = atomicAdd(&g_cur[d4.w], 1);
        g_ssrc[p0] = s4.x;
        g_ssrc[p1] = s4.y;
        g_ssrc[p2] = s4.z;
        g_ssrc[p3] = s4.w;
    }
}

// ---------------- tf32 (single-pass) tensor-core GEMM ----------------------
// Inputs converted to tf32 ONCE at staging; inner loop is pure LDS + MMA.
// y==0: W=src_w -> fp16 into g_comb ha-slots (+ x fp16 into comb x-slots).
// y==1: W=dst_w -> fp16 g_xproj (with bias).
__device__ __forceinline__ uint32_t f2tf(float f) {
    uint32_t u;
    asm("cvt.rna.tf32.f32 %0, %1;" : "=r"(u) : "f"(f));
    return u;
}

__device__ __forceinline__ void mma_tf32(float* c, const uint32_t* a, const uint32_t* b) {
    asm volatile(
        "mma.sync.aligned.m16n8k8.row.col.f32.tf32.tf32.f32 "
        "{%0,%1,%2,%3}, {%4,%5,%6,%7}, {%8,%9}, {%0,%1,%2,%3};"
        : "+f"(c[0]), "+f"(c[1]), "+f"(c[2]), "+f"(c[3])
        : "r"(a[0]), "r"(a[1]), "r"(a[2]), "r"(a[3]), "r"(b[0]), "r"(b[1]));
}

#define SMSTRIDE 132
#define GEMM_SMEM (2 * 128 * SMSTRIDE * 4)

__global__ __launch_bounds__(256) void gemm_tc_kernel(
    const float* __restrict__ x,
    const float* __restrict__ src_w, const float* __restrict__ dst_w,
    const float* __restrict__ src_b, const float* __restrict__ dst_b) {
    extern __shared__ uint32_t smu[];
    uint32_t* As = smu;                      // tf32 bits, 128 x SMSTRIDE
    uint32_t* Ws = smu + 128 * SMSTRIDE;     // tf32 bits, row = k

    const float* W    = (blockIdx.y == 0) ? src_w : dst_w;
    const float* bias = (blockIdx.y == 0) ? src_b : dst_b;

    int tid = threadIdx.x;
    int rowBase = blockIdx.x * 128;
    char* combBase = (char*)g_comb;

#pragma unroll
    for (int it = 0; it < 16; it++) {
        int idx = tid + it * 256;
        int r = idx >> 5;
        int c = (idx & 31) * 4;
        float4 v = make_float4(0.f, 0.f, 0.f, 0.f);
        bool inb = (rowBase + r < N_NODES);
        if (inb)
            v = *(const float4*)&x[(long long)(rowBase + r) * DIM + c];
        As[r * SMSTRIDE + c + 0] = f2tf(v.x);
        As[r * SMSTRIDE + c + 1] = f2tf(v.y);
        As[r * SMSTRIDE + c + 2] = f2tf(v.z);
        As[r * SMSTRIDE + c + 3] = f2tf(v.w);
        if (blockIdx.y == 0 && inb) {
            __half2 h0 = __floats2half2_rn(v.x, v.y);
            __half2 h1 = __floats2half2_rn(v.z, v.w);
            uint2 u = make_uint2(*(uint32_t*)&h0, *(uint32_t*)&h1);
            *(uint2*)(combBase + (long long)(rowBase + r) * 512 + (c >> 2) * 16) = u;
        }
        float4 wv = *(const float4*)&W[(long long)r * DIM + c];
        Ws[r * SMSTRIDE + c + 0] = f2tf(wv.x);
        Ws[r * SMSTRIDE + c + 1] = f2tf(wv.y);
        Ws[r * SMSTRIDE + c + 2] = f2tf(wv.z);
        Ws[r * SMSTRIDE + c + 3] = f2tf(wv.w);
    }
    __syncthreads();

    int wid = tid >> 5, lane = tid & 31;
    int g = lane >> 2, t = lane & 3;
    int warpM = wid & 3, warpN = wid >> 2;
    int wrow = warpM * 32, wcol = warpN * 64;

    float acc[2][8][4];
#pragma unroll
    for (int mt = 0; mt < 2; mt++)
#pragma unroll
        for (int nt = 0; nt < 8; nt++)
#pragma unroll
            for (int j = 0; j < 4; j++) acc[mt][nt][j] = 0.0f;

    for (int kt = 0; kt < 16; kt++) {
        int k0 = kt * 8;
        uint32_t a[2][4];
#pragma unroll
        for (int mt = 0; mt < 2; mt++) {
            int r0 = wrow + mt * 16;
            a[mt][0] = As[(r0 + g) * SMSTRIDE + k0 + t];
            a[mt][1] = As[(r0 + g + 8) * SMSTRIDE + k0 + t];
            a[mt][2] = As[(r0 + g) * SMSTRIDE + k0 + t + 4];
            a[mt][3] = As[(r0 + g + 8) * SMSTRIDE + k0 + t + 4];
        }
        uint32_t b[8][2];
#pragma unroll
        for (int nt = 0; nt < 8; nt++) {
            int col = wcol + nt * 8 + g;
            b[nt][0] = Ws[(k0 + t) * SMSTRIDE + col];
            b[nt][1] = Ws[(k0 + t + 4) * SMSTRIDE + col];
        }
#pragma unroll
        for (int mt = 0; mt < 2; mt++)
#pragma unroll
            for (int nt = 0; nt < 8; nt++)
                mma_tf32(acc[mt][nt], a[mt], b[nt]);
    }

    bool toComb = (blockIdx.y == 0);
#pragma unroll
    for (int mt = 0; mt < 2; mt++) {
#pragma unroll
        for (int nt = 0; nt < 8; nt++) {
            int col = wcol + nt * 8 + 2 * t;
            float b0 = bias[col], b1 = bias[col + 1];
            int row0 = rowBase + wrow + mt * 16 + g;
            int row1 = row0 + 8;
            __half2 h0 = __floats2half2_rn(acc[mt][nt][0] + b0, acc[mt][nt][1] + b1);
            __half2 h1 = __floats2half2_rn(acc[mt][nt][2] + b0, acc[mt][nt][3] + b1);
            if (toComb) {
                long long off0 = (long long)row0 * 512 + (col >> 2) * 16 + 8 + (col & 3) * 2;
                long long off1 = (long long)row1 * 512 + (col >> 2) * 16 + 8 + (col & 3) * 2;
                if (row0 < N_NODES) *(__half2*)((char*)g_comb + off0) = h0;
                if (row1 < N_NODES) *(__half2*)((char*)g_comb + off1) = h1;
            } else {
                if (row0 < N_NODES) *(__half2*)&g_xproj[(long long)row0 * DIM + col] = h0;
                if (row1 < N_NODES) *(__half2*)&g_xproj[(long long)row1 * DIM + col] = h1;
            }
        }
    }
}

// ------- k3: fused mean(xproj) + score + denom + weighted output -----------
__global__ __launch_bounds__(256) void fused_out_kernel(
    const float* __restrict__ att_w,
    const float* __restrict__ att_b,
    float* __restrict__ out) {
    int warp = (blockIdx.x * blockDim.x + threadIdx.x) >> 5;
    int lane = threadIdx.x & 31;
    if (warp >= N_NODES) return;
    int beg = g_off[warp];
    int end = g_off[warp + 1];

    // ---- loop 1: ha_dst row (mean of xproj[src]) in registers ----
    float4 bacc = make_float4(0.f, 0.f, 0.f, 0.f);
    int p = beg;
    for (; p + 3 < end; p += 4) {
        int s0 = g_ssrc[p], s1 = g_ssrc[p + 1], s2 = g_ssrc[p + 2], s3 = g_ssrc[p + 3];
        uint2 r0 = *(const uint2*)&g_xproj[(long long)s0 * DIM + lane * 4];
        uint2 r1 = *(const uint2*)&g_xproj[(long long)s1 * DIM + lane * 4];
        uint2 r2 = *(const uint2*)&g_xproj[(long long)s2 * DIM + lane * 4];
        uint2 r3 = *(const uint2*)&g_xproj[(long long)s3 * DIM + lane * 4];
        float2 f0a = __half22float2(*(__half2*)&r0.x), f0b = __half22float2(*(__half2*)&r0.y);
        float2 f1a = __half22float2(*(__half2*)&r1.x), f1b = __half22float2(*(__half2*)&r1.y);
        float2 f2a = __half22float2(*(__half2*)&r2.x), f2b = __half22float2(*(__half2*)&r2.y);
        float2 f3a = __half22float2(*(__half2*)&r3.x), f3b = __half22float2(*(__half2*)&r3.y);
        bacc.x += f0a.x + f1a.x + f2a.x + f3a.x;
        bacc.y += f0a.y + f1a.y + f2a.y + f3a.y;
        bacc.z += f0b.x + f1b.x + f2b.x + f3b.x;
        bacc.w += f0b.y + f1b.y + f2b.y + f3b.y;
    }
    for (; p < end; p++) {
        int s = g_ssrc[p];
        uint2 r = *(const uint2*)&g_xproj[(long long)s * DIM + lane * 4];
        float2 fa = __half22float2(*(__half2*)&r.x), fb = __half22float2(*(__half2*)&r.y);
        bacc.x += fa.x; bacc.y += fa.y; bacc.z += fb.x; bacc.w += fb.y;
    }
    float rm = 1.0f / (float)max(end - beg, 1);
    float4 b = make_float4(bacc.x * rm, bacc.y * rm, bacc.z * rm, bacc.w * rm);

    float4 w = *(const float4*)&att_w[lane * 4];
    float  c = att_b[0];

    // ---- loop 2: scores + denom + weighted output ----
    float denom = 0.0f;
    float4 o = make_float4(0.f, 0.f, 0.f, 0.f);
    p = beg;
    for (; p + 1 < end; p += 2) {
        int s0 = g_ssrc[p], s1 = g_ssrc[p + 1];
        uint4 c0 = g_comb[(long long)s0 * 32 + lane];
        uint4 c1 = g_comb[(long long)s1 * 32 + lane];
        float2 x0a = __half22float2(*(__half2*)&c0.x);
        float2 x0b = __half22float2(*(__half2*)&c0.y);
        float2 a0a = __half22float2(*(__half2*)&c0.z);
        float2 a0b = __half22float2(*(__half2*)&c0.w);
        float2 x1a = __half22float2(*(__half2*)&c1.x);
        float2 x1b = __half22float2(*(__half2*)&c1.y);
        float2 a1a = __half22float2(*(__half2*)&c1.z);
        float2 a1b = __half22float2(*(__half2*)&c1.w);
        float t0, t1;
        {
            float v0 = a0a.x + b.x, v1 = a0a.y + b.y, v2 = a0b.x + b.z, v3 = a0b.y + b.w;
            v0 = (v0 >= 0.f) ? v0 : v0 * NEG_SLOPE;
            v1 = (v1 >= 0.f) ? v1 : v1 * NEG_SLOPE;
            v2 = (v2 >= 0.f) ? v2 : v2 * NEG_SLOPE;
            v3 = (v3 >= 0.f) ? v3 : v3 * NEG_SLOPE;
            t0 = v0 * w.x + v1 * w.y + v2 * w.z + v3 * w.w;
        }
        {
            float v0 = a1a.x + b.x, v1 = a1a.y + b.y, v2 = a1b.x + b.z, v3 = a1b.y + b.w;
            v0 = (v0 >= 0.f) ? v0 : v0 * NEG_SLOPE;
            v1 = (v1 >= 0.f) ? v1 : v1 * NEG_SLOPE;
            v2 = (v2 >= 0.f) ? v2 : v2 * NEG_SLOPE;
            v3 = (v3 >= 0.f) ? v3 : v3 * NEG_SLOPE;
            t1 = v0 * w.x + v1 * w.y + v2 * w.z + v3 * w.w;
        }
#pragma unroll
        for (int off = 16; off > 0; off >>= 1) {
            t0 += __shfl_xor_sync(0xFFFFFFFFu, t0, off);
            t1 += __shfl_xor_sync(0xFFFFFFFFu, t1, off);
        }
        float sv0 = expf(t0 + c);
        float sv1 = expf(t1 + c);
        denom += sv0 + sv1;
        o.x += sv0 * x0a.x + sv1 * x1a.x;
        o.y += sv0 * x0a.y + sv1 * x1a.y;
        o.z += sv0 * x0b.x + sv1 * x1b.x;
        o.w += sv0 * x0b.y + sv1 * x1b.y;
    }
    for (; p < end; p++) {
        int s = g_ssrc[p];
        uint4 cc = g_comb[(long long)s * 32 + lane];
        float2 xa = __half22float2(*(__half2*)&cc.x);
        float2 xb = __half22float2(*(__half2*)&cc.y);
        float2 aa = __half22float2(*(__half2*)&cc.z);
        float2 ab = __half22float2(*(__half2*)&cc.w);
        float v0 = aa.x + b.x, v1 = aa.y + b.y, v2 = ab.x + b.z, v3 = ab.y + b.w;
        v0 = (v0 >= 0.f) ? v0 : v0 * NEG_SLOPE;
        v1 = (v1 >= 0.f) ? v1 : v1 * NEG_SLOPE;
        v2 = (v2 >= 0.f) ? v2 : v2 * NEG_SLOPE;
        v3 = (v3 >= 0.f) ? v3 : v3 * NEG_SLOPE;
        float t = v0 * w.x + v1 * w.y + v2 * w.z + v3 * w.w;
#pragma unroll
        for (int off = 16; off > 0; off >>= 1)
            t += __shfl_xor_sync(0xFFFFFFFFu, t, off);
        float sv = expf(t + c);
        denom += sv;
        o.x += sv * xa.x; o.y += sv * xa.y; o.z += sv * xb.x; o.w += sv * xb.y;
    }

    float rd = (end > beg) ? 1.0f / denom : 0.0f;
    float4 r = make_float4(o.x * rd, o.y * rd, o.z * rd, o.w * rd);
    *(float4*)&out[(long long)warp * DIM + lane * 4] = r;
}

// ---------------------------------------------------------------------------
extern "C" void kernel_launch(void* const* d_in, const int* in_sizes, int n_in,
                              void* d_out, int out_size) {
    const float* x       = (const float*)d_in[0];
    const int*   src_idx = (const int*)d_in[1];
    const int*   dst_idx = (const int*)d_in[2];
    const float* src_w   = (const float*)d_in[3];
    const float* src_b   = (const float*)d_in[4];
    const float* dst_w   = (const float*)d_in[5];
    const float* dst_b   = (const float*)d_in[6];
    const float* att_w   = (const float*)d_in[7];
    const float* att_b   = (const float*)d_in[8];
    float* out = (float*)d_out;

    (void)in_sizes; (void)n_in; (void)out_size;

    static cudaStream_t s2 = nullptr;
    static cudaEvent_t evFork = nullptr, evJoin = nullptr;
    if (s2 == nullptr) {
        cudaStreamCreateWithFlags(&s2, cudaStreamNonBlocking);
        cudaEventCreateWithFlags(&evFork, cudaEventDisableTiming);
        cudaEventCreateWithFlags(&evJoin, cudaEventDisableTiming);
        cudaFuncSetAttribute(gemm_tc_kernel,
                             cudaFuncAttributeMaxDynamicSharedMemorySize, GEMM_SMEM);
    }

    const int nodeWarpBlocks = (N_NODES * 32 + 255) / 256;

    // fork: GEMM branch (x + weights only; also produces comb x-halves)
    cudaEventRecord(evFork, 0);
    cudaStreamWaitEvent(s2, evFork, 0);
    dim3 gemmGrid((N_NODES + 127) / 128, 2);
    gemm_tc_kernel<<<gemmGrid, 256, GEMM_SMEM, s2>>>(x, src_w, dst_w, src_b, dst_b);
    cudaEventRecord(evJoin, s2);

    // main branch: one persistent CSR build kernel
    csr_kernel<<<CSR_BLOCKS, CSR_THREADS>>>(src_idx, dst_idx);

    // join
    cudaStreamWaitEvent(0, evJoin, 0);
    fused_out_kernel<<<nodeWarpBlocks, 256>>>(att_w, att_b, out);
}

// round 12
// speedup vs baseline: 1.4235x; 1.1205x over previous
#include <cuda_runtime.h>
#include <cuda_bf16.h>
#include <cuda_fp16.h>
#include <cstdint>

#define N_NODES 50000
#define N_EDGES 800000
#define DIM 128
#define NEG_SLOPE 0.01f

#define CSR_BLOCKS 592
#define CSR_THREADS 256
#define TILE 1024
#define NT ((N_NODES + TILE - 1) / TILE)   // 49

// ---------------- scratch (device globals; no allocation allowed) ----------
__device__ int    g_cnt[N_NODES];          // self-restoring: zeroed by scan phase
__device__ int    g_off[N_NODES + 1];
__device__ int    g_cur[N_NODES];
__device__ int    g_part[64];
__device__ int    g_ssrc[N_EDGES];
// interleaved per-node record: 32 chunks x 16B; chunk c = {x[4c..4c+3] fp16, ha_src[4c..4c+3] fp16}
__device__ uint4  g_comb[N_NODES * 32];
__device__ __half g_xproj[N_NODES * DIM];  // fp16 (x @ dst_w + dst_b)
__device__ int    g_bar_count;
__device__ int    g_bar_gen;

// ---------------- software grid barrier (all blocks resident) --------------
__device__ __forceinline__ void grid_barrier() {
    __syncthreads();
    if (threadIdx.x == 0) {
        int gen = *(volatile int*)&g_bar_gen;
        __threadfence();
        int arrived = atomicAdd(&g_bar_count, 1);
        if (arrived == (int)gridDim.x - 1) {
            g_bar_count = 0;
            __threadfence();
            *(volatile int*)&g_bar_gen = gen + 1;
        } else {
            while (*(volatile int*)&g_bar_gen == gen) __nanosleep(100);
        }
        __threadfence();
    }
    __syncthreads();
}

// ---------------- k1: persistent CSR build (hist -> scan -> scatter) -------
__global__ __launch_bounds__(CSR_THREADS) void csr_kernel(
    const int* __restrict__ src, const int* __restrict__ dst) {
    int tid = threadIdx.x;
    int gthread = blockIdx.x * CSR_THREADS + tid;
    const int gstride = CSR_BLOCKS * CSR_THREADS;

    // ---- phase 1: histogram ----
    for (int slot = gthread; slot < N_EDGES / 4; slot += gstride) {
        int4 d4 = *(const int4*)&dst[slot * 4];
        atomicAdd(&g_cnt[d4.x], 1);
        atomicAdd(&g_cnt[d4.y], 1);
        atomicAdd(&g_cnt[d4.z], 1);
        atomicAdd(&g_cnt[d4.w], 1);
    }
    grid_barrier();

    // ---- phase 2a: tile sums ----
    __shared__ int sh[64];
    __shared__ int warpsum[8];
    if (blockIdx.x < NT) {
        int base = blockIdx.x * TILE;
        int idx = base + tid * 4;
        int s = 0;
#pragma unroll
        for (int k = 0; k < 4; k++)
            if (idx + k < N_NODES) s += g_cnt[idx + k];
#pragma unroll
        for (int off = 16; off > 0; off >>= 1)
            s += __shfl_xor_sync(0xFFFFFFFFu, s, off);
        if ((tid & 31) == 0) warpsum[tid >> 5] = s;
        __syncthreads();
        if (tid < 8) {
            int t = warpsum[tid];
#pragma unroll
            for (int off = 4; off > 0; off >>= 1)
                t += __shfl_xor_sync(0xFFu, t, off);
            if (tid == 0) g_part[blockIdx.x] = t;
        }
    }
    grid_barrier();

    // ---- phase 2b: exclusive scan of NT tile sums ----
    if (blockIdx.x == 0) {
        int v = 0;
        if (tid < 64) {
            v = (tid < NT) ? g_part[tid] : 0;
            sh[tid] = v;
        }
        __syncthreads();
        for (int off = 1; off < 64; off <<= 1) {
            int t = 0;
            if (tid < 64 && tid >= off) t = sh[tid - off];
            __syncthreads();
            if (tid < 64) sh[tid] += t;
            __syncthreads();
        }
        if (tid < NT) g_part[tid] = sh[tid] - v;
    }
    grid_barrier();

    // ---- phase 2c: local scan + offsets; zero g_cnt ----
    if (blockIdx.x < NT) {
        int base = blockIdx.x * TILE;
        int idx = base + tid * 4;
        int c0 = 0, c1 = 0, c2 = 0, c3 = 0;
        if (idx + 0 < N_NODES) c0 = g_cnt[idx + 0];
        if (idx + 1 < N_NODES) c1 = g_cnt[idx + 1];
        if (idx + 2 < N_NODES) c2 = g_cnt[idx + 2];
        if (idx + 3 < N_NODES) c3 = g_cnt[idx + 3];
        int mysum = c0 + c1 + c2 + c3;
        int lane = tid & 31, wid = tid >> 5;
        int incl = mysum;
#pragma unroll
        for (int off = 1; off < 32; off <<= 1) {
            int t = __shfl_up_sync(0xFFFFFFFFu, incl, off);
            if (lane >= off) incl += t;
        }
        if (lane == 31) warpsum[wid] = incl;
        __syncthreads();
        if (wid == 0) {
            int s = (lane < 8) ? warpsum[lane] : 0;
#pragma unroll
            for (int off = 1; off < 8; off <<= 1) {
                int t = __shfl_up_sync(0xFFFFFFFFu, s, off);
                if (lane >= off) s += t;
            }
            if (lane < 8) warpsum[lane] = s;
        }
        __syncthreads();
        int warpExcl = (wid > 0) ? warpsum[wid - 1] : 0;
        int excl = incl - mysum + warpExcl + g_part[blockIdx.x];
        int o0 = excl, o1 = o0 + c0, o2 = o1 + c1, o3 = o2 + c2;
        if (idx + 0 < N_NODES) { g_off[idx + 0] = o0; g_cur[idx + 0] = o0; g_cnt[idx + 0] = 0; }
        if (idx + 1 < N_NODES) { g_off[idx + 1] = o1; g_cur[idx + 1] = o1; g_cnt[idx + 1] = 0; }
        if (idx + 2 < N_NODES) { g_off[idx + 2] = o2; g_cur[idx + 2] = o2; g_cnt[idx + 2] = 0; }
        if (idx + 3 < N_NODES) { g_off[idx + 3] = o3; g_cur[idx + 3] = o3; g_cnt[idx + 3] = 0; }
        if (blockIdx.x == 0 && tid == 0) g_off[N_NODES] = N_EDGES;
    }
    grid_barrier();

    // ---- phase 3: scatter ----
    for (int slot = gthread; slot < N_EDGES / 4; slot += gstride) {
        int4 d4 = *(const int4*)&dst[slot * 4];
        int4 s4 = *(const int4*)&src[slot * 4];
        int p0 = atomicAdd(&g_cur[d4.x], 1);
        int p1 = atomicAdd(&g_cur[d4.y], 1);
        int p2 = atomicAdd(&g_cur[d4.z], 1);
        int p3 = atomicAdd(&g_cur[d4.w], 1);
        g_ssrc[p0] = s4.x;
        g_ssrc[p1] = s4.y;
        g_ssrc[p2] = s4.z;
        g_ssrc[p3] = s4.w;
    }
}

// ---------------- fp16 tensor-core GEMM (m16n8k16, ldmatrix) ---------------
// y==0: W=src_w -> fp16 into g_comb ha-slots (+ x fp16 into comb x-slots).
// y==1: W=dst_w -> fp16 g_xproj (with bias). fp32 accumulate.
__device__ __forceinline__ void mma_f16(float* c, const uint32_t* a, const uint32_t* b) {
    asm volatile(
        "mma.sync.aligned.m16n8k16.row.col.f32.f16.f16.f32 "
        "{%0,%1,%2,%3}, {%4,%5,%6,%7}, {%8,%9}, {%0,%1,%2,%3};"
        : "+f"(c[0]), "+f"(c[1]), "+f"(c[2]), "+f"(c[3])
        : "r"(a[0]), "r"(a[1]), "r"(a[2]), "r"(a[3]), "r"(b[0]), "r"(b[1]));
}

#define HSTRIDE 136                        // halves per row (128 + 8 pad)
#define GEMM_SMEM (2 * 128 * HSTRIDE * 2)  // 69632 bytes

__global__ __launch_bounds__(256) void gemm_tc_kernel(
    const float* __restrict__ x,
    const float* __restrict__ src_w, const float* __restrict__ dst_w,
    const float* __restrict__ src_b, const float* __restrict__ dst_b) {
    extern __shared__ __half smh[];
    __half* As = smh;                   // [row 0..127][HSTRIDE]  (row-major, k contiguous)
    __half* Ws = smh + 128 * HSTRIDE;   // [k 0..127][HSTRIDE]    (row-major, n contiguous)

    const float* W    = (blockIdx.y == 0) ? src_w : dst_w;
    const float* bias = (blockIdx.y == 0) ? src_b : dst_b;

    int tid = threadIdx.x;
    int rowBase = blockIdx.x * 128;
    char* combBase = (char*)g_comb;

    // ---- staging: fp32 -> fp16 into smem (uint2 = 4 halves per store) ----
#pragma unroll
    for (int it = 0; it < 16; it++) {
        int idx = tid + it * 256;
        int r = idx >> 5;               // row (A) / k (W)
        int c = (idx & 31) * 4;         // k col (A) / n col (W)
        float4 v = make_float4(0.f, 0.f, 0.f, 0.f);
        bool inb = (rowBase + r < N_NODES);
        if (inb)
            v = *(const float4*)&x[(long long)(rowBase + r) * DIM + c];
        __half2 h0 = __floats2half2_rn(v.x, v.y);
        __half2 h1 = __floats2half2_rn(v.z, v.w);
        uint2 u = make_uint2(*(uint32_t*)&h0, *(uint32_t*)&h1);
        *(uint2*)&As[r * HSTRIDE + c] = u;
        if (blockIdx.y == 0 && inb)
            *(uint2*)(combBase + (long long)(rowBase + r) * 512 + (c >> 2) * 16) = u;
        float4 wv = *(const float4*)&W[(long long)r * DIM + c];
        __half2 w0 = __floats2half2_rn(wv.x, wv.y);
        __half2 w1 = __floats2half2_rn(wv.z, wv.w);
        uint2 uw = make_uint2(*(uint32_t*)&w0, *(uint32_t*)&w1);
        *(uint2*)&Ws[r * HSTRIDE + c] = uw;
    }
    __syncthreads();

    int wid = tid >> 5, lane = tid & 31;
    int g = lane >> 2, t = lane & 3;
    int warpM = wid & 3, warpN = wid >> 2;
    int wrow = warpM * 32, wcol = warpN * 64;

    int l15 = lane & 15;
    int aColOff = (lane >> 4) << 3;     // 0 or 8 (halves)

    float acc[2][8][4];
#pragma unroll
    for (int mt = 0; mt < 2; mt++)
#pragma unroll
        for (int nt = 0; nt < 8; nt++)
#pragma unroll
            for (int j = 0; j < 4; j++) acc[mt][nt][j] = 0.0f;

#pragma unroll
    for (int kt = 0; kt < 8; kt++) {
        int k0 = kt * 16;
        uint32_t a[2][4];
#pragma unroll
        for (int mt = 0; mt < 2; mt++) {
            const __half* p = &As[(wrow + mt * 16 + l15) * HSTRIDE + k0 + aColOff];
            uint32_t sa = (uint32_t)__cvta_generic_to_shared(p);
            asm volatile(
                "ldmatrix.sync.aligned.m8n8.x4.shared.b16 {%0,%1,%2,%3}, [%4];"
                : "=r"(a[mt][0]), "=r"(a[mt][1]), "=r"(a[mt][2]), "=r"(a[mt][3])
                : "r"(sa));
        }
        uint32_t b[8][2];
#pragma unroll
        for (int nt = 0; nt < 8; nt++) {
            const __half* p = &Ws[(k0 + l15) * HSTRIDE + wcol + nt * 8];
            uint32_t sb = (uint32_t)__cvta_generic_to_shared(p);
            asm volatile(
                "ldmatrix.sync.aligned.m8n8.x2.trans.shared.b16 {%0,%1}, [%2];"
                : "=r"(b[nt][0]), "=r"(b[nt][1])
                : "r"(sb));
        }
#pragma unroll
        for (int mt = 0; mt < 2; mt++)
#pragma unroll
            for (int nt = 0; nt < 8; nt++)
                mma_f16(acc[mt][nt], a[mt], b[nt]);
    }

    bool toComb = (blockIdx.y == 0);
#pragma unroll
    for (int mt = 0; mt < 2; mt++) {
#pragma unroll
        for (int nt = 0; nt < 8; nt++) {
            int col = wcol + nt * 8 + 2 * t;
            float b0 = bias[col], b1 = bias[col + 1];
            int row0 = rowBase + wrow + mt * 16 + g;
            int row1 = row0 + 8;
            __half2 h0 = __floats2half2_rn(acc[mt][nt][0] + b0, acc[mt][nt][1] + b1);
            __half2 h1 = __floats2half2_rn(acc[mt][nt][2] + b0, acc[mt][nt][3] + b1);
            if (toComb) {
                long long off0 = (long long)row0 * 512 + (col >> 2) * 16 + 8 + (col & 3) * 2;
                long long off1 = (long long)row1 * 512 + (col >> 2) * 16 + 8 + (col & 3) * 2;
                if (row0 < N_NODES) *(__half2*)((char*)g_comb + off0) = h0;
                if (row1 < N_NODES) *(__half2*)((char*)g_comb + off1) = h1;
            } else {
                if (row0 < N_NODES) *(__half2*)&g_xproj[(long long)row0 * DIM + col] = h0;
                if (row1 < N_NODES) *(__half2*)&g_xproj[(long long)row1 * DIM + col] = h1;
            }
        }
    }
}

// ------- k3: fused mean(xproj) + score + denom + weighted output -----------
__global__ __launch_bounds__(256) void fused_out_kernel(
    const float* __restrict__ att_w,
    const float* __restrict__ att_b,
    float* __restrict__ out) {
    int warp = (blockIdx.x * blockDim.x + threadIdx.x) >> 5;
    int lane = threadIdx.x & 31;
    if (warp >= N_NODES) return;
    int beg = g_off[warp];
    int end = g_off[warp + 1];

    // ---- loop 1: ha_dst row (mean of xproj[src]) in registers ----
    float4 bacc = make_float4(0.f, 0.f, 0.f, 0.f);
    int p = beg;
    for (; p + 3 < end; p += 4) {
        int s0 = g_ssrc[p], s1 = g_ssrc[p + 1], s2 = g_ssrc[p + 2], s3 = g_ssrc[p + 3];
        uint2 r0 = *(const uint2*)&g_xproj[(long long)s0 * DIM + lane * 4];
        uint2 r1 = *(const uint2*)&g_xproj[(long long)s1 * DIM + lane * 4];
        uint2 r2 = *(const uint2*)&g_xproj[(long long)s2 * DIM + lane * 4];
        uint2 r3 = *(const uint2*)&g_xproj[(long long)s3 * DIM + lane * 4];
        float2 f0a = __half22float2(*(__half2*)&r0.x), f0b = __half22float2(*(__half2*)&r0.y);
        float2 f1a = __half22float2(*(__half2*)&r1.x), f1b = __half22float2(*(__half2*)&r1.y);
        float2 f2a = __half22float2(*(__half2*)&r2.x), f2b = __half22float2(*(__half2*)&r2.y);
        float2 f3a = __half22float2(*(__half2*)&r3.x), f3b = __half22float2(*(__half2*)&r3.y);
        bacc.x += f0a.x + f1a.x + f2a.x + f3a.x;
        bacc.y += f0a.y + f1a.y + f2a.y + f3a.y;
        bacc.z += f0b.x + f1b.x + f2b.x + f3b.x;
        bacc.w += f0b.y + f1b.y + f2b.y + f3b.y;
    }
    for (; p < end; p++) {
        int s = g_ssrc[p];
        uint2 r = *(const uint2*)&g_xproj[(long long)s * DIM + lane * 4];
        float2 fa = __half22float2(*(__half2*)&r.x), fb = __half22float2(*(__half2*)&r.y);
        bacc.x += fa.x; bacc.y += fa.y; bacc.z += fb.x; bacc.w += fb.y;
    }
    float rm = 1.0f / (float)max(end - beg, 1);
    float4 b = make_float4(bacc.x * rm, bacc.y * rm, bacc.z * rm, bacc.w * rm);

    float4 w = *(const float4*)&att_w[lane * 4];
    float  c = att_b[0];

    // ---- loop 2: scores + denom + weighted output ----
    float denom = 0.0f;
    float4 o = make_float4(0.f, 0.f, 0.f, 0.f);
    p = beg;
    for (; p + 1 < end; p += 2) {
        int s0 = g_ssrc[p], s1 = g_ssrc[p + 1];
        uint4 c0 = g_comb[(long long)s0 * 32 + lane];
        uint4 c1 = g_comb[(long long)s1 * 32 + lane];
        float2 x0a = __half22float2(*(__half2*)&c0.x);
        float2 x0b = __half22float2(*(__half2*)&c0.y);
        float2 a0a = __half22float2(*(__half2*)&c0.z);
        float2 a0b = __half22float2(*(__half2*)&c0.w);
        float2 x1a = __half22float2(*(__half2*)&c1.x);
        float2 x1b = __half22float2(*(__half2*)&c1.y);
        float2 a1a = __half22float2(*(__half2*)&c1.z);
        float2 a1b = __half22float2(*(__half2*)&c1.w);
        float t0, t1;
        {
            float v0 = a0a.x + b.x, v1 = a0a.y + b.y, v2 = a0b.x + b.z, v3 = a0b.y + b.w;
            v0 = (v0 >= 0.f) ? v0 : v0 * NEG_SLOPE;
            v1 = (v1 >= 0.f) ? v1 : v1 * NEG_SLOPE;
            v2 = (v2 >= 0.f) ? v2 : v2 * NEG_SLOPE;
            v3 = (v3 >= 0.f) ? v3 : v3 * NEG_SLOPE;
            t0 = v0 * w.x + v1 * w.y + v2 * w.z + v3 * w.w;
        }
        {
            float v0 = a1a.x + b.x, v1 = a1a.y + b.y, v2 = a1b.x + b.z, v3 = a1b.y + b.w;
            v0 = (v0 >= 0.f) ? v0 : v0 * NEG_SLOPE;
            v1 = (v1 >= 0.f) ? v1 : v1 * NEG_SLOPE;
            v2 = (v2 >= 0.f) ? v2 : v2 * NEG_SLOPE;
            v3 = (v3 >= 0.f) ? v3 : v3 * NEG_SLOPE;
            t1 = v0 * w.x + v1 * w.y + v2 * w.z + v3 * w.w;
        }
#pragma unroll
        for (int off = 16; off > 0; off >>= 1) {
            t0 += __shfl_xor_sync(0xFFFFFFFFu, t0, off);
            t1 += __shfl_xor_sync(0xFFFFFFFFu, t1, off);
        }
        float sv0 = expf(t0 + c);
        float sv1 = expf(t1 + c);
        denom += sv0 + sv1;
        o.x += sv0 * x0a.x + sv1 * x1a.x;
        o.y += sv0 * x0a.y + sv1 * x1a.y;
        o.z += sv0 * x0b.x + sv1 * x1b.x;
        o.w += sv0 * x0b.y + sv1 * x1b.y;
    }
    for (; p < end; p++) {
        int s = g_ssrc[p];
        uint4 cc = g_comb[(long long)s * 32 + lane];
        float2 xa = __half22float2(*(__half2*)&cc.x);
        float2 xb = __half22float2(*(__half2*)&cc.y);
        float2 aa = __half22float2(*(__half2*)&cc.z);
        float2 ab = __half22float2(*(__half2*)&cc.w);
        float v0 = aa.x + b.x, v1 = aa.y + b.y, v2 = ab.x + b.z, v3 = ab.y + b.w;
        v0 = (v0 >= 0.f) ? v0 : v0 * NEG_SLOPE;
        v1 = (v1 >= 0.f) ? v1 : v1 * NEG_SLOPE;
        v2 = (v2 >= 0.f) ? v2 : v2 * NEG_SLOPE;
        v3 = (v3 >= 0.f) ? v3 : v3 * NEG_SLOPE;
        float t = v0 * w.x + v1 * w.y + v2 * w.z + v3 * w.w;
#pragma unroll
        for (int off = 16; off > 0; off >>= 1)
            t += __shfl_xor_sync(0xFFFFFFFFu, t, off);
        float sv = expf(t + c);
        denom += sv;
        o.x += sv * xa.x; o.y += sv * xa.y; o.z += sv * xb.x; o.w += sv * xb.y;
    }

    float rd = (end > beg) ? 1.0f / denom : 0.0f;
    float4 r = make_float4(o.x * rd, o.y * rd, o.z * rd, o.w * rd);
    *(float4*)&out[(long long)warp * DIM + lane * 4] = r;
}

// ---------------------------------------------------------------------------
extern "C" void kernel_launch(void* const* d_in, const int* in_sizes, int n_in,
                              void* d_out, int out_size) {
    const float* x       = (const float*)d_in[0];
    const int*   src_idx = (const int*)d_in[1];
    const int*   dst_idx = (const int*)d_in[2];
    const float* src_w   = (const float*)d_in[3];
    const float* src_b   = (const float*)d_in[4];
    const float* dst_w   = (const float*)d_in[5];
    const float* dst_b   = (const float*)d_in[6];
    const float* att_w   = (const float*)d_in[7];
    const float* att_b   = (const float*)d_in[8];
    float* out = (float*)d_out;

    (void)in_sizes; (void)n_in; (void)out_size;

    static cudaStream_t s2 = nullptr;
    static cudaEvent_t evFork = nullptr, evJoin = nullptr;
    if (s2 == nullptr) {
        cudaStreamCreateWithFlags(&s2, cudaStreamNonBlocking);
        cudaEventCreateWithFlags(&evFork, cudaEventDisableTiming);
        cudaEventCreateWithFlags(&evJoin, cudaEventDisableTiming);
        cudaFuncSetAttribute(gemm_tc_kernel,
                             cudaFuncAttributeMaxDynamicSharedMemorySize, GEMM_SMEM);
    }

    const int nodeWarpBlocks = (N_NODES * 32 + 255) / 256;

    // fork: GEMM branch (x + weights only; also produces comb x-halves)
    cudaEventRecord(evFork, 0);
    cudaStreamWaitEvent(s2, evFork, 0);
    dim3 gemmGrid((N_NODES + 127) / 128, 2);
    gemm_tc_kernel<<<gemmGrid, 256, GEMM_SMEM, s2>>>(x, src_w, dst_w, src_b, dst_b);
    cudaEventRecord(evJoin, s2);

    // main branch: one persistent CSR build kernel
    csr_kernel<<<CSR_BLOCKS, CSR_THREADS>>>(src_idx, dst_idx);

    // join
    cudaStreamWaitEvent(0, evJoin, 0);
    fused_out_kernel<<<nodeWarpBlocks, 256>>>(att_w, att_b, out);
}

// round 13
// speedup vs baseline: 1.4813x; 1.0406x over previous
#include <cuda_runtime.h>
#include <cuda_bf16.h>
#include <cuda_fp16.h>
#include <cstdint>

#define N_NODES 50000
#define N_EDGES 800000
#define DIM 128
#define NEG_SLOPE 0.01f

#define CSR_BLOCKS 592
#define CSR_THREADS 256
#define TILE 1024
#define NT ((N_NODES + TILE - 1) / TILE)   // 49

// ---------------- scratch (device globals; no allocation allowed) ----------
__device__ int    g_cnt[N_NODES];          // self-restoring: zeroed by scan phase
__device__ int    g_off[N_NODES + 1];
__device__ int    g_cur[N_NODES];
__device__ int    g_part[64];
__device__ int    g_ssrc[N_EDGES];
// interleaved per-node record: 32 chunks x 16B; chunk c = {x[4c..4c+3] fp16, ha_src[4c..4c+3] fp16}
__device__ uint4  g_comb[N_NODES * 32];
__device__ __half g_xproj[N_NODES * DIM];  // fp16 (x @ dst_w + dst_b)
__device__ int    g_bar_count;
__device__ int    g_bar_gen;

// ---------------- software grid barrier (all blocks resident) --------------
__device__ __forceinline__ void grid_barrier() {
    __syncthreads();
    if (threadIdx.x == 0) {
        int gen = *(volatile int*)&g_bar_gen;
        __threadfence();
        int arrived = atomicAdd(&g_bar_count, 1);
        if (arrived == (int)gridDim.x - 1) {
            g_bar_count = 0;
            __threadfence();
            *(volatile int*)&g_bar_gen = gen + 1;
        } else {
            while (*(volatile int*)&g_bar_gen == gen) __nanosleep(100);
        }
        __threadfence();
    }
    __syncthreads();
}

// ---------------- k1: persistent CSR build (hist -> scan -> scatter) -------
__global__ __launch_bounds__(CSR_THREADS) void csr_kernel(
    const int* __restrict__ src, const int* __restrict__ dst) {
    int tid = threadIdx.x;
    int gthread = blockIdx.x * CSR_THREADS + tid;
    const int gstride = CSR_BLOCKS * CSR_THREADS;

    // ---- phase 1: histogram ----
    for (int slot = gthread; slot < N_EDGES / 4; slot += gstride) {
        int4 d4 = *(const int4*)&dst[slot * 4];
        atomicAdd(&g_cnt[d4.x], 1);
        atomicAdd(&g_cnt[d4.y], 1);
        atomicAdd(&g_cnt[d4.z], 1);
        atomicAdd(&g_cnt[d4.w], 1);
    }
    grid_barrier();

    // ---- phase 2a: tile sums ----
    __shared__ int sh[64];
    __shared__ int warpsum[8];
    if (blockIdx.x < NT) {
        int base = blockIdx.x * TILE;
        int idx = base + tid * 4;
        int s = 0;
#pragma unroll
        for (int k = 0; k < 4; k++)
            if (idx + k < N_NODES) s += g_cnt[idx + k];
#pragma unroll
        for (int off = 16; off > 0; off >>= 1)
            s += __shfl_xor_sync(0xFFFFFFFFu, s, off);
        if ((tid & 31) == 0) warpsum[tid >> 5] = s;
        __syncthreads();
        if (tid < 8) {
            int t = warpsum[tid];
#pragma unroll
            for (int off = 4; off > 0; off >>= 1)
                t += __shfl_xor_sync(0xFFu, t, off);
            if (tid == 0) g_part[blockIdx.x] = t;
        }
    }
    grid_barrier();

    // ---- phase 2b: exclusive scan of NT tile sums ----
    if (blockIdx.x == 0) {
        int v = 0;
        if (tid < 64) {
            v = (tid < NT) ? g_part[tid] : 0;
            sh[tid] = v;
        }
        __syncthreads();
        for (int off = 1; off < 64; off <<= 1) {
            int t = 0;
            if (tid < 64 && tid >= off) t = sh[tid - off];
            __syncthreads();
            if (tid < 64) sh[tid] += t;
            __syncthreads();
        }
        if (tid < NT) g_part[tid] = sh[tid] - v;
    }
    grid_barrier();

    // ---- phase 2c: local scan + offsets; zero g_cnt ----
    if (blockIdx.x < NT) {
        int base = blockIdx.x * TILE;
        int idx = base + tid * 4;
        int c0 = 0, c1 = 0, c2 = 0, c3 = 0;
        if (idx + 0 < N_NODES) c0 = g_cnt[idx + 0];
        if (idx + 1 < N_NODES) c1 = g_cnt[idx + 1];
        if (idx + 2 < N_NODES) c2 = g_cnt[idx + 2];
        if (idx + 3 < N_NODES) c3 = g_cnt[idx + 3];
        int mysum = c0 + c1 + c2 + c3;
        int lane = tid & 31, wid = tid >> 5;
        int incl = mysum;
#pragma unroll
        for (int off = 1; off < 32; off <<= 1) {
            int t = __shfl_up_sync(0xFFFFFFFFu, incl, off);
            if (lane >= off) incl += t;
        }
        if (lane == 31) warpsum[wid] = incl;
        __syncthreads();
        if (wid == 0) {
            int s = (lane < 8) ? warpsum[lane] : 0;
#pragma unroll
            for (int off = 1; off < 8; off <<= 1) {
                int t = __shfl_up_sync(0xFFFFFFFFu, s, off);
                if (lane >= off) s += t;
            }
            if (lane < 8) warpsum[lane] = s;
        }
        __syncthreads();
        int warpExcl = (wid > 0) ? warpsum[wid - 1] : 0;
        int excl = incl - mysum + warpExcl + g_part[blockIdx.x];
        int o0 = excl, o1 = o0 + c0, o2 = o1 + c1, o3 = o2 + c2;
        if (idx + 0 < N_NODES) { g_off[idx + 0] = o0; g_cur[idx + 0] = o0; g_cnt[idx + 0] = 0; }
        if (idx + 1 < N_NODES) { g_off[idx + 1] = o1; g_cur[idx + 1] = o1; g_cnt[idx + 1] = 0; }
        if (idx + 2 < N_NODES) { g_off[idx + 2] = o2; g_cur[idx + 2] = o2; g_cnt[idx + 2] = 0; }
        if (idx + 3 < N_NODES) { g_off[idx + 3] = o3; g_cur[idx + 3] = o3; g_cnt[idx + 3] = 0; }
        if (blockIdx.x == 0 && tid == 0) g_off[N_NODES] = N_EDGES;
    }
    grid_barrier();

    // ---- phase 3: scatter ----
    for (int slot = gthread; slot < N_EDGES / 4; slot += gstride) {
        int4 d4 = *(const int4*)&dst[slot * 4];
        int4 s4 = *(const int4*)&src[slot * 4];
        int p0 = atomicAdd(&g_cur[d4.x], 1);
        int p1 = atomicAdd(&g_cur[d4.y], 1);
        int p2 = atomicAdd(&g_cur[d4.z], 1);
        int p3 = atomicAdd(&g_cur[d4.w], 1);
        g_ssrc[p0] = s4.x;
        g_ssrc[p1] = s4.y;
        g_ssrc[p2] = s4.z;
        g_ssrc[p3] = s4.w;
    }
}

// ---------------- fp16 tensor-core GEMM (m16n8k16, ldmatrix) ---------------
__device__ __forceinline__ void mma_f16(float* c, const uint32_t* a, const uint32_t* b) {
    asm volatile(
        "mma.sync.aligned.m16n8k16.row.col.f32.f16.f16.f32 "
        "{%0,%1,%2,%3}, {%4,%5,%6,%7}, {%8,%9}, {%0,%1,%2,%3};"
        : "+f"(c[0]), "+f"(c[1]), "+f"(c[2]), "+f"(c[3])
        : "r"(a[0]), "r"(a[1]), "r"(a[2]), "r"(a[3]), "r"(b[0]), "r"(b[1]));
}

#define HSTRIDE 136                        // halves per row (128 + 8 pad)
#define GEMM_SMEM (2 * 128 * HSTRIDE * 2)  // 69632 bytes

__global__ __launch_bounds__(256) void gemm_tc_kernel(
    const float* __restrict__ x,
    const float* __restrict__ src_w, const float* __restrict__ dst_w,
    const float* __restrict__ src_b, const float* __restrict__ dst_b) {
    extern __shared__ __half smh[];
    __half* As = smh;                   // [row 0..127][HSTRIDE]
    __half* Ws = smh + 128 * HSTRIDE;   // [k 0..127][HSTRIDE]

    const float* W    = (blockIdx.y == 0) ? src_w : dst_w;
    const float* bias = (blockIdx.y == 0) ? src_b : dst_b;

    int tid = threadIdx.x;
    int rowBase = blockIdx.x * 128;
    char* combBase = (char*)g_comb;

#pragma unroll
    for (int it = 0; it < 16; it++) {
        int idx = tid + it * 256;
        int r = idx >> 5;
        int c = (idx & 31) * 4;
        float4 v = make_float4(0.f, 0.f, 0.f, 0.f);
        bool inb = (rowBase + r < N_NODES);
        if (inb)
            v = *(const float4*)&x[(long long)(rowBase + r) * DIM + c];
        __half2 h0 = __floats2half2_rn(v.x, v.y);
        __half2 h1 = __floats2half2_rn(v.z, v.w);
        uint2 u = make_uint2(*(uint32_t*)&h0, *(uint32_t*)&h1);
        *(uint2*)&As[r * HSTRIDE + c] = u;
        if (blockIdx.y == 0 && inb)
            *(uint2*)(combBase + (long long)(rowBase + r) * 512 + (c >> 2) * 16) = u;
        float4 wv = *(const float4*)&W[(long long)r * DIM + c];
        __half2 w0 = __floats2half2_rn(wv.x, wv.y);
        __half2 w1 = __floats2half2_rn(wv.z, wv.w);
        uint2 uw = make_uint2(*(uint32_t*)&w0, *(uint32_t*)&w1);
        *(uint2*)&Ws[r * HSTRIDE + c] = uw;
    }
    __syncthreads();

    int wid = tid >> 5, lane = tid & 31;
    int g = lane >> 2, t = lane & 3;
    int warpM = wid & 3, warpN = wid >> 2;
    int wrow = warpM * 32, wcol = warpN * 64;

    int l15 = lane & 15;
    int aColOff = (lane >> 4) << 3;

    float acc[2][8][4];
#pragma unroll
    for (int mt = 0; mt < 2; mt++)
#pragma unroll
        for (int nt = 0; nt < 8; nt++)
#pragma unroll
            for (int j = 0; j < 4; j++) acc[mt][nt][j] = 0.0f;

#pragma unroll
    for (int kt = 0; kt < 8; kt++) {
        int k0 = kt * 16;
        uint32_t a[2][4];
#pragma unroll
        for (int mt = 0; mt < 2; mt++) {
            const __half* p = &As[(wrow + mt * 16 + l15) * HSTRIDE + k0 + aColOff];
            uint32_t sa = (uint32_t)__cvta_generic_to_shared(p);
            asm volatile(
                "ldmatrix.sync.aligned.m8n8.x4.shared.b16 {%0,%1,%2,%3}, [%4];"
                : "=r"(a[mt][0]), "=r"(a[mt][1]), "=r"(a[mt][2]), "=r"(a[mt][3])
                : "r"(sa));
        }
        uint32_t b[8][2];
#pragma unroll
        for (int nt = 0; nt < 8; nt++) {
            const __half* p = &Ws[(k0 + l15) * HSTRIDE + wcol + nt * 8];
            uint32_t sb = (uint32_t)__cvta_generic_to_shared(p);
            asm volatile(
                "ldmatrix.sync.aligned.m8n8.x2.trans.shared.b16 {%0,%1}, [%2];"
                : "=r"(b[nt][0]), "=r"(b[nt][1])
                : "r"(sb));
        }
#pragma unroll
        for (int mt = 0; mt < 2; mt++)
#pragma unroll
            for (int nt = 0; nt < 8; nt++)
                mma_f16(acc[mt][nt], a[mt], b[nt]);
    }

    bool toComb = (blockIdx.y == 0);
#pragma unroll
    for (int mt = 0; mt < 2; mt++) {
#pragma unroll
        for (int nt = 0; nt < 8; nt++) {
            int col = wcol + nt * 8 + 2 * t;
            float b0 = bias[col], b1 = bias[col + 1];
            int row0 = rowBase + wrow + mt * 16 + g;
            int row1 = row0 + 8;
            __half2 h0 = __floats2half2_rn(acc[mt][nt][0] + b0, acc[mt][nt][1] + b1);
            __half2 h1 = __floats2half2_rn(acc[mt][nt][2] + b0, acc[mt][nt][3] + b1);
            if (toComb) {
                long long off0 = (long long)row0 * 512 + (col >> 2) * 16 + 8 + (col & 3) * 2;
                long long off1 = (long long)row1 * 512 + (col >> 2) * 16 + 8 + (col & 3) * 2;
                if (row0 < N_NODES) *(__half2*)((char*)g_comb + off0) = h0;
                if (row1 < N_NODES) *(__half2*)((char*)g_comb + off1) = h1;
            } else {
                if (row0 < N_NODES) *(__half2*)&g_xproj[(long long)row0 * DIM + col] = h0;
                if (row1 < N_NODES) *(__half2*)&g_xproj[(long long)row1 * DIM + col] = h1;
            }
        }
    }
}

// ------- k3: fused mean(xproj) + score + denom + weighted output -----------
// Score helper: per-lane partial dot of leakyrelu(a + b) with w.
__device__ __forceinline__ float score_part(uint4 cc, float4 b, float4 w,
                                            float2& xa, float2& xb) {
    xa = __half22float2(*(__half2*)&cc.x);
    xb = __half22float2(*(__half2*)&cc.y);
    float2 aa = __half22float2(*(__half2*)&cc.z);
    float2 ab = __half22float2(*(__half2*)&cc.w);
    float v0 = aa.x + b.x, v1 = aa.y + b.y, v2 = ab.x + b.z, v3 = ab.y + b.w;
    v0 = (v0 >= 0.f) ? v0 : v0 * NEG_SLOPE;
    v1 = (v1 >= 0.f) ? v1 : v1 * NEG_SLOPE;
    v2 = (v2 >= 0.f) ? v2 : v2 * NEG_SLOPE;
    v3 = (v3 >= 0.f) ? v3 : v3 * NEG_SLOPE;
    return v0 * w.x + v1 * w.y + v2 * w.z + v3 * w.w;
}

__global__ __launch_bounds__(256) void fused_out_kernel(
    const float* __restrict__ att_w,
    const float* __restrict__ att_b,
    float* __restrict__ out) {
    int warp = (blockIdx.x * blockDim.x + threadIdx.x) >> 5;
    int lane = threadIdx.x & 31;
    if (warp >= N_NODES) return;
    int beg = g_off[warp];
    int end = g_off[warp + 1];

    // ---- loop 1: ha_dst row (mean of xproj[src]) in registers ----
    float4 bacc = make_float4(0.f, 0.f, 0.f, 0.f);
    int p = beg;
    for (; p + 3 < end; p += 4) {
        int s0 = g_ssrc[p], s1 = g_ssrc[p + 1], s2 = g_ssrc[p + 2], s3 = g_ssrc[p + 3];
        uint2 r0 = *(const uint2*)&g_xproj[(long long)s0 * DIM + lane * 4];
        uint2 r1 = *(const uint2*)&g_xproj[(long long)s1 * DIM + lane * 4];
        uint2 r2 = *(const uint2*)&g_xproj[(long long)s2 * DIM + lane * 4];
        uint2 r3 = *(const uint2*)&g_xproj[(long long)s3 * DIM + lane * 4];
        float2 f0a = __half22float2(*(__half2*)&r0.x), f0b = __half22float2(*(__half2*)&r0.y);
        float2 f1a = __half22float2(*(__half2*)&r1.x), f1b = __half22float2(*(__half2*)&r1.y);
        float2 f2a = __half22float2(*(__half2*)&r2.x), f2b = __half22float2(*(__half2*)&r2.y);
        float2 f3a = __half22float2(*(__half2*)&r3.x), f3b = __half22float2(*(__half2*)&r3.y);
        bacc.x += f0a.x + f1a.x + f2a.x + f3a.x;
        bacc.y += f0a.y + f1a.y + f2a.y + f3a.y;
        bacc.z += f0b.x + f1b.x + f2b.x + f3b.x;
        bacc.w += f0b.y + f1b.y + f2b.y + f3b.y;
    }
    for (; p < end; p++) {
        int s = g_ssrc[p];
        uint2 r = *(const uint2*)&g_xproj[(long long)s * DIM + lane * 4];
        float2 fa = __half22float2(*(__half2*)&r.x), fb = __half22float2(*(__half2*)&r.y);
        bacc.x += fa.x; bacc.y += fa.y; bacc.z += fb.x; bacc.w += fb.y;
    }
    float rm = 1.0f / (float)max(end - beg, 1);
    float4 b = make_float4(bacc.x * rm, bacc.y * rm, bacc.z * rm, bacc.w * rm);

    float4 w = *(const float4*)&att_w[lane * 4];
    float  cb = att_b[0];

    // ---- loop 2: scores + denom + weighted output (ILP-4) ----
    float denom = 0.0f;
    float4 o = make_float4(0.f, 0.f, 0.f, 0.f);
    p = beg;
    for (; p + 3 < end; p += 4) {
        int s0 = g_ssrc[p], s1 = g_ssrc[p + 1], s2 = g_ssrc[p + 2], s3 = g_ssrc[p + 3];
        uint4 c0 = g_comb[(long long)s0 * 32 + lane];
        uint4 c1 = g_comb[(long long)s1 * 32 + lane];
        uint4 c2 = g_comb[(long long)s2 * 32 + lane];
        uint4 c3 = g_comb[(long long)s3 * 32 + lane];
        float2 x0a, x0b, x1a, x1b, x2a, x2b, x3a, x3b;
        float t0 = score_part(c0, b, w, x0a, x0b);
        float t1 = score_part(c1, b, w, x1a, x1b);
        float t2 = score_part(c2, b, w, x2a, x2b);
        float t3 = score_part(c3, b, w, x3a, x3b);
        // 4 interleaved butterfly trees — one 5-step latency for all 4 edges
#pragma unroll
        for (int off = 16; off > 0; off >>= 1) {
            t0 += __shfl_xor_sync(0xFFFFFFFFu, t0, off);
            t1 += __shfl_xor_sync(0xFFFFFFFFu, t1, off);
            t2 += __shfl_xor_sync(0xFFFFFFFFu, t2, off);
            t3 += __shfl_xor_sync(0xFFFFFFFFu, t3, off);
        }
        float sv0 = __expf(t0 + cb);
        float sv1 = __expf(t1 + cb);
        float sv2 = __expf(t2 + cb);
        float sv3 = __expf(t3 + cb);
        denom += (sv0 + sv1) + (sv2 + sv3);
        o.x += sv0 * x0a.x + sv1 * x1a.x + sv2 * x2a.x + sv3 * x3a.x;
        o.y += sv0 * x0a.y + sv1 * x1a.y + sv2 * x2a.y + sv3 * x3a.y;
        o.z += sv0 * x0b.x + sv1 * x1b.x + sv2 * x2b.x + sv3 * x3b.x;
        o.w += sv0 * x0b.y + sv1 * x1b.y + sv2 * x2b.y + sv3 * x3b.y;
    }
    for (; p < end; p++) {
        int s = g_ssrc[p];
        uint4 cc = g_comb[(long long)s * 32 + lane];
        float2 xa, xb;
        float t = score_part(cc, b, w, xa, xb);
#pragma unroll
        for (int off = 16; off > 0; off >>= 1)
            t += __shfl_xor_sync(0xFFFFFFFFu, t, off);
        float sv = __expf(t + cb);
        denom += sv;
        o.x += sv * xa.x; o.y += sv * xa.y; o.z += sv * xb.x; o.w += sv * xb.y;
    }

    float rd = (end > beg) ? 1.0f / denom : 0.0f;
    float4 r = make_float4(o.x * rd, o.y * rd, o.z * rd, o.w * rd);
    *(float4*)&out[(long long)warp * DIM + lane * 4] = r;
}

// ---------------------------------------------------------------------------
extern "C" void kernel_launch(void* const* d_in, const int* in_sizes, int n_in,
                              void* d_out, int out_size) {
    const float* x       = (const float*)d_in[0];
    const int*   src_idx = (const int*)d_in[1];
    const int*   dst_idx = (const int*)d_in[2];
    const float* src_w   = (const float*)d_in[3];
    const float* src_b   = (const float*)d_in[4];
    const float* dst_w   = (const float*)d_in[5];
    const float* dst_b   = (const float*)d_in[6];
    const float* att_w   = (const float*)d_in[7];
    const float* att_b   = (const float*)d_in[8];
    float* out = (float*)d_out;

    (void)in_sizes; (void)n_in; (void)out_size;

    static cudaStream_t s2 = nullptr;
    static cudaEvent_t evFork = nullptr, evJoin = nullptr;
    if (s2 == nullptr) {
        cudaStreamCreateWithFlags(&s2, cudaStreamNonBlocking);
        cudaEventCreateWithFlags(&evFork, cudaEventDisableTiming);
        cudaEventCreateWithFlags(&evJoin, cudaEventDisableTiming);
        cudaFuncSetAttribute(gemm_tc_kernel,
                             cudaFuncAttributeMaxDynamicSharedMemorySize, GEMM_SMEM);
    }

    const int nodeWarpBlocks = (N_NODES * 32 + 255) / 256;

    // fork: GEMM branch (x + weights only; also produces comb x-halves)
    cudaEventRecord(evFork, 0);
    cudaStreamWaitEvent(s2, evFork, 0);
    dim3 gemmGrid((N_NODES + 127) / 128, 2);
    gemm_tc_kernel<<<gemmGrid, 256, GEMM_SMEM, s2>>>(x, src_w, dst_w, src_b, dst_b);
    cudaEventRecord(evJoin, s2);

    // main branch: one persistent CSR build kernel
    csr_kernel<<<CSR_BLOCKS, CSR_THREADS>>>(src_idx, dst_idx);

    // join
    cudaStreamWaitEvent(0, evJoin, 0);
    fused_out_kernel<<<nodeWarpBlocks, 256>>>(att_w, att_b, out);
}

// round 14
// speedup vs baseline: 1.5029x; 1.0145x over previous
#include <cuda_runtime.h>
#include <cuda_bf16.h>
#include <cuda_fp16.h>
#include <cstdint>

#define N_NODES 50000
#define N_EDGES 800000
#define DIM 128
#define NEG_SLOPE 0.01f

#define CSR_BLOCKS 592
#define CSR_THREADS 256
#define TILE 1024
#define NT ((N_NODES + TILE - 1) / TILE)   // 49

// ---------------- scratch (device globals; no allocation allowed) ----------
__device__ int    g_cnt[N_NODES];          // self-restoring: zeroed by scan phase
__device__ int    g_off[N_NODES + 1];
__device__ int    g_cur[N_NODES];
__device__ int    g_part[64];
__device__ int    g_ssrc[N_EDGES];
// interleaved per-node record: 32 chunks x 16B; chunk c = {x[4c..4c+3] fp16, ha_src[4c..4c+3] fp16}
__device__ uint4  g_comb[N_NODES * 32];
__device__ __half g_xproj[N_NODES * DIM];  // fp16 (x @ dst_w + dst_b)
__device__ int    g_bar_count;
__device__ int    g_bar_gen;

// ---------------- software grid barrier (all blocks resident) --------------
__device__ __forceinline__ void grid_barrier() {
    __syncthreads();
    if (threadIdx.x == 0) {
        int gen = *(volatile int*)&g_bar_gen;
        __threadfence();
        int arrived = atomicAdd(&g_bar_count, 1);
        if (arrived == (int)gridDim.x - 1) {
            g_bar_count = 0;
            __threadfence();
            *(volatile int*)&g_bar_gen = gen + 1;
        } else {
            while (*(volatile int*)&g_bar_gen == gen) __nanosleep(40);
        }
        __threadfence();
    }
    __syncthreads();
}

// ---------------- k1: persistent CSR build (hist -> scan -> scatter) -------
__global__ __launch_bounds__(CSR_THREADS) void csr_kernel(
    const int* __restrict__ src, const int* __restrict__ dst) {
    int tid = threadIdx.x;
    int lane = tid & 31, wid = tid >> 5;
    int gthread = blockIdx.x * CSR_THREADS + tid;
    const int gstride = CSR_BLOCKS * CSR_THREADS;

    // ---- phase 1: histogram ----
    for (int slot = gthread; slot < N_EDGES / 4; slot += gstride) {
        int4 d4 = *(const int4*)&dst[slot * 4];
        atomicAdd(&g_cnt[d4.x], 1);
        atomicAdd(&g_cnt[d4.y], 1);
        atomicAdd(&g_cnt[d4.z], 1);
        atomicAdd(&g_cnt[d4.w], 1);
    }
    grid_barrier();

    // ---- phase 2a: tile sums (blocks 0..NT-1) ----
    __shared__ int warpsum[8];
    __shared__ int sh_excl[64];
    if (blockIdx.x < NT) {
        int base = blockIdx.x * TILE;
        int idx = base + tid * 4;
        int s = 0;
#pragma unroll
        for (int k = 0; k < 4; k++)
            if (idx + k < N_NODES) s += g_cnt[idx + k];
#pragma unroll
        for (int off = 16; off > 0; off >>= 1)
            s += __shfl_xor_sync(0xFFFFFFFFu, s, off);
        if (lane == 0) warpsum[wid] = s;
        __syncthreads();
        if (tid < 8) {
            int t = warpsum[tid];
#pragma unroll
            for (int off = 4; off > 0; off >>= 1)
                t += __shfl_xor_sync(0xFFu, t, off);
            if (tid == 0) g_part[blockIdx.x] = t;
        }
    }
    grid_barrier();

    // ---- phase 2c: blockOff via warp-parallel scan of partials,
    //      local exclusive scan + offsets; zero g_cnt (restore) ----
    if (blockIdx.x < NT) {
        // warp 0: exclusive prefix of the NT tile sums (parallel, ~0.3us)
        if (wid == 0) {
            int v0 = (lane < NT) ? g_part[lane] : 0;
            int v1 = (lane + 32 < NT) ? g_part[lane + 32] : 0;
            int s0 = v0;
#pragma unroll
            for (int off = 1; off < 32; off <<= 1) {
                int t = __shfl_up_sync(0xFFFFFFFFu, s0, off);
                if (lane >= off) s0 += t;
            }
            int tot0 = __shfl_sync(0xFFFFFFFFu, s0, 31);
            int s1 = v1;
#pragma unroll
            for (int off = 1; off < 32; off <<= 1) {
                int t = __shfl_up_sync(0xFFFFFFFFu, s1, off);
                if (lane >= off) s1 += t;
            }
            s1 += tot0;
            sh_excl[lane] = s0 - v0;
            sh_excl[lane + 32] = s1 - v1;
        }

        int base = blockIdx.x * TILE;
        int idx = base + tid * 4;
        int c0 = 0, c1 = 0, c2 = 0, c3 = 0;
        if (idx + 0 < N_NODES) c0 = g_cnt[idx + 0];
        if (idx + 1 < N_NODES) c1 = g_cnt[idx + 1];
        if (idx + 2 < N_NODES) c2 = g_cnt[idx + 2];
        if (idx + 3 < N_NODES) c3 = g_cnt[idx + 3];
        int mysum = c0 + c1 + c2 + c3;
        int incl = mysum;
#pragma unroll
        for (int off = 1; off < 32; off <<= 1) {
            int t = __shfl_up_sync(0xFFFFFFFFu, incl, off);
            if (lane >= off) incl += t;
        }
        if (lane == 31) warpsum[wid] = incl;
        __syncthreads();
        if (wid == 0) {
            int s = (lane < 8) ? warpsum[lane] : 0;
#pragma unroll
            for (int off = 1; off < 8; off <<= 1) {
                int t = __shfl_up_sync(0xFFFFFFFFu, s, off);
                if (lane >= off) s += t;
            }
            if (lane < 8) warpsum[lane] = s;
        }
        __syncthreads();
        int warpExcl = (wid > 0) ? warpsum[wid - 1] : 0;
        int excl = incl - mysum + warpExcl + sh_excl[blockIdx.x];
        int o0 = excl, o1 = o0 + c0, o2 = o1 + c1, o3 = o2 + c2;
        if (idx + 0 < N_NODES) { g_off[idx + 0] = o0; g_cur[idx + 0] = o0; g_cnt[idx + 0] = 0; }
        if (idx + 1 < N_NODES) { g_off[idx + 1] = o1; g_cur[idx + 1] = o1; g_cnt[idx + 1] = 0; }
        if (idx + 2 < N_NODES) { g_off[idx + 2] = o2; g_cur[idx + 2] = o2; g_cnt[idx + 2] = 0; }
        if (idx + 3 < N_NODES) { g_off[idx + 3] = o3; g_cur[idx + 3] = o3; g_cnt[idx + 3] = 0; }
        if (blockIdx.x == 0 && tid == 0) g_off[N_NODES] = N_EDGES;
    }
    grid_barrier();

    // ---- phase 3: scatter ----
    for (int slot = gthread; slot < N_EDGES / 4; slot += gstride) {
        int4 d4 = *(const int4*)&dst[slot * 4];
        int4 s4 = *(const int4*)&src[slot * 4];
        int p0 = atomicAdd(&g_cur[d4.x], 1);
        int p1 = atomicAdd(&g_cur[d4.y], 1);
        int p2 = atomicAdd(&g_cur[d4.z], 1);
        int p3 = atomicAdd(&g_cur[d4.w], 1);
        g_ssrc[p0] = s4.x;
        g_ssrc[p1] = s4.y;
        g_ssrc[p2] = s4.z;
        g_ssrc[p3] = s4.w;
    }
}

// ---------------- fp16 tensor-core GEMM (m16n8k16, ldmatrix) ---------------
__device__ __forceinline__ void mma_f16(float* c, const uint32_t* a, const uint32_t* b) {
    asm volatile(
        "mma.sync.aligned.m16n8k16.row.col.f32.f16.f16.f32 "
        "{%0,%1,%2,%3}, {%4,%5,%6,%7}, {%8,%9}, {%0,%1,%2,%3};"
        : "+f"(c[0]), "+f"(c[1]), "+f"(c[2]), "+f"(c[3])
        : "r"(a[0]), "r"(a[1]), "r"(a[2]), "r"(a[3]), "r"(b[0]), "r"(b[1]));
}

#define HSTRIDE 136                        // halves per row (128 + 8 pad)
#define GEMM_SMEM (2 * 128 * HSTRIDE * 2)  // 69632 bytes

__global__ __launch_bounds__(256) void gemm_tc_kernel(
    const float* __restrict__ x,
    const float* __restrict__ src_w, const float* __restrict__ dst_w,
    const float* __restrict__ src_b, const float* __restrict__ dst_b) {
    extern __shared__ __half smh[];
    __half* As = smh;                   // [row 0..127][HSTRIDE]
    __half* Ws = smh + 128 * HSTRIDE;   // [k 0..127][HSTRIDE]

    const float* W    = (blockIdx.y == 0) ? src_w : dst_w;
    const float* bias = (blockIdx.y == 0) ? src_b : dst_b;

    int tid = threadIdx.x;
    int rowBase = blockIdx.x * 128;
    char* combBase = (char*)g_comb;

#pragma unroll
    for (int it = 0; it < 16; it++) {
        int idx = tid + it * 256;
        int r = idx >> 5;
        int c = (idx & 31) * 4;
        float4 v = make_float4(0.f, 0.f, 0.f, 0.f);
        bool inb = (rowBase + r < N_NODES);
        if (inb)
            v = *(const float4*)&x[(long long)(rowBase + r) * DIM + c];
        __half2 h0 = __floats2half2_rn(v.x, v.y);
        __half2 h1 = __floats2half2_rn(v.z, v.w);
        uint2 u = make_uint2(*(uint32_t*)&h0, *(uint32_t*)&h1);
        *(uint2*)&As[r * HSTRIDE + c] = u;
        if (blockIdx.y == 0 && inb)
            *(uint2*)(combBase + (long long)(rowBase + r) * 512 + (c >> 2) * 16) = u;
        float4 wv = *(const float4*)&W[(long long)r * DIM + c];
        __half2 w0 = __floats2half2_rn(wv.x, wv.y);
        __half2 w1 = __floats2half2_rn(wv.z, wv.w);
        uint2 uw = make_uint2(*(uint32_t*)&w0, *(uint32_t*)&w1);
        *(uint2*)&Ws[r * HSTRIDE + c] = uw;
    }
    __syncthreads();

    int wid = tid >> 5, lane = tid & 31;
    int g = lane >> 2, t = lane & 3;
    int warpM = wid & 3, warpN = wid >> 2;
    int wrow = warpM * 32, wcol = warpN * 64;

    int l15 = lane & 15;
    int aColOff = (lane >> 4) << 3;

    float acc[2][8][4];
#pragma unroll
    for (int mt = 0; mt < 2; mt++)
#pragma unroll
        for (int nt = 0; nt < 8; nt++)
#pragma unroll
            for (int j = 0; j < 4; j++) acc[mt][nt][j] = 0.0f;

#pragma unroll
    for (int kt = 0; kt < 8; kt++) {
        int k0 = kt * 16;
        uint32_t a[2][4];
#pragma unroll
        for (int mt = 0; mt < 2; mt++) {
            const __half* p = &As[(wrow + mt * 16 + l15) * HSTRIDE + k0 + aColOff];
            uint32_t sa = (uint32_t)__cvta_generic_to_shared(p);
            asm volatile(
                "ldmatrix.sync.aligned.m8n8.x4.shared.b16 {%0,%1,%2,%3}, [%4];"
                : "=r"(a[mt][0]), "=r"(a[mt][1]), "=r"(a[mt][2]), "=r"(a[mt][3])
                : "r"(sa));
        }
        uint32_t b[8][2];
#pragma unroll
        for (int nt = 0; nt < 8; nt++) {
            const __half* p = &Ws[(k0 + l15) * HSTRIDE + wcol + nt * 8];
            uint32_t sb = (uint32_t)__cvta_generic_to_shared(p);
            asm volatile(
                "ldmatrix.sync.aligned.m8n8.x2.trans.shared.b16 {%0,%1}, [%2];"
                : "=r"(b[nt][0]), "=r"(b[nt][1])
                : "r"(sb));
        }
#pragma unroll
        for (int mt = 0; mt < 2; mt++)
#pragma unroll
            for (int nt = 0; nt < 8; nt++)
                mma_f16(acc[mt][nt], a[mt], b[nt]);
    }

    bool toComb = (blockIdx.y == 0);
#pragma unroll
    for (int mt = 0; mt < 2; mt++) {
#pragma unroll
        for (int nt = 0; nt < 8; nt++) {
            int col = wcol + nt * 8 + 2 * t;
            float b0 = bias[col], b1 = bias[col + 1];
            int row0 = rowBase + wrow + mt * 16 + g;
            int row1 = row0 + 8;
            __half2 h0 = __floats2half2_rn(acc[mt][nt][0] + b0, acc[mt][nt][1] + b1);
            __half2 h1 = __floats2half2_rn(acc[mt][nt][2] + b0, acc[mt][nt][3] + b1);
            if (toComb) {
                long long off0 = (long long)row0 * 512 + (col >> 2) * 16 + 8 + (col & 3) * 2;
                long long off1 = (long long)row1 * 512 + (col >> 2) * 16 + 8 + (col & 3) * 2;
                if (row0 < N_NODES) *(__half2*)((char*)g_comb + off0) = h0;
                if (row1 < N_NODES) *(__half2*)((char*)g_comb + off1) = h1;
            } else {
                if (row0 < N_NODES) *(__half2*)&g_xproj[(long long)row0 * DIM + col] = h0;
                if (row1 < N_NODES) *(__half2*)&g_xproj[(long long)row1 * DIM + col] = h1;
            }
        }
    }
}

// ------- k3: fused mean(xproj) + score + denom + weighted output -----------
__device__ __forceinline__ float score_part(uint4 cc, float4 b, float4 w,
                                            float2& xa, float2& xb) {
    xa = __half22float2(*(__half2*)&cc.x);
    xb = __half22float2(*(__half2*)&cc.y);
    float2 aa = __half22float2(*(__half2*)&cc.z);
    float2 ab = __half22float2(*(__half2*)&cc.w);
    float v0 = aa.x + b.x, v1 = aa.y + b.y, v2 = ab.x + b.z, v3 = ab.y + b.w;
    v0 = (v0 >= 0.f) ? v0 : v0 * NEG_SLOPE;
    v1 = (v1 >= 0.f) ? v1 : v1 * NEG_SLOPE;
    v2 = (v2 >= 0.f) ? v2 : v2 * NEG_SLOPE;
    v3 = (v3 >= 0.f) ? v3 : v3 * NEG_SLOPE;
    return v0 * w.x + v1 * w.y + v2 * w.z + v3 * w.w;
}

__global__ __launch_bounds__(256, 3) void fused_out_kernel(
    const float* __restrict__ att_w,
    const float* __restrict__ att_b,
    float* __restrict__ out) {
    int warp = (blockIdx.x * blockDim.x + threadIdx.x) >> 5;
    int lane = threadIdx.x & 31;
    if (warp >= N_NODES) return;
    int beg = g_off[warp];
    int end = g_off[warp + 1];

    // ---- loop 1: ha_dst row (mean of xproj[src]) in registers ----
    float4 bacc = make_float4(0.f, 0.f, 0.f, 0.f);
    int p = beg;
    for (; p + 3 < end; p += 4) {
        int s0 = g_ssrc[p], s1 = g_ssrc[p + 1], s2 = g_ssrc[p + 2], s3 = g_ssrc[p + 3];
        uint2 r0 = *(const uint2*)&g_xproj[(long long)s0 * DIM + lane * 4];
        uint2 r1 = *(const uint2*)&g_xproj[(long long)s1 * DIM + lane * 4];
        uint2 r2 = *(const uint2*)&g_xproj[(long long)s2 * DIM + lane * 4];
        uint2 r3 = *(const uint2*)&g_xproj[(long long)s3 * DIM + lane * 4];
        float2 f0a = __half22float2(*(__half2*)&r0.x), f0b = __half22float2(*(__half2*)&r0.y);
        float2 f1a = __half22float2(*(__half2*)&r1.x), f1b = __half22float2(*(__half2*)&r1.y);
        float2 f2a = __half22float2(*(__half2*)&r2.x), f2b = __half22float2(*(__half2*)&r2.y);
        float2 f3a = __half22float2(*(__half2*)&r3.x), f3b = __half22float2(*(__half2*)&r3.y);
        bacc.x += f0a.x + f1a.x + f2a.x + f3a.x;
        bacc.y += f0a.y + f1a.y + f2a.y + f3a.y;
        bacc.z += f0b.x + f1b.x + f2b.x + f3b.x;
        bacc.w += f0b.y + f1b.y + f2b.y + f3b.y;
    }
    for (; p < end; p++) {
        int s = g_ssrc[p];
        uint2 r = *(const uint2*)&g_xproj[(long long)s * DIM + lane * 4];
        float2 fa = __half22float2(*(__half2*)&r.x), fb = __half22float2(*(__half2*)&r.y);
        bacc.x += fa.x; bacc.y += fa.y; bacc.z += fb.x; bacc.w += fb.y;
    }
    float rm = 1.0f / (float)max(end - beg, 1);
    float4 b = make_float4(bacc.x * rm, bacc.y * rm, bacc.z * rm, bacc.w * rm);

    float4 w = *(const float4*)&att_w[lane * 4];
    float  cb = att_b[0];

    // ---- loop 2: scores + denom + weighted output (ILP-4) ----
    float denom = 0.0f;
    float4 o = make_float4(0.f, 0.f, 0.f, 0.f);
    p = beg;
    for (; p + 3 < end; p += 4) {
        int s0 = g_ssrc[p], s1 = g_ssrc[p + 1], s2 = g_ssrc[p + 2], s3 = g_ssrc[p + 3];
        uint4 c0 = g_comb[(long long)s0 * 32 + lane];
        uint4 c1 = g_comb[(long long)s1 * 32 + lane];
        uint4 c2 = g_comb[(long long)s2 * 32 + lane];
        uint4 c3 = g_comb[(long long)s3 * 32 + lane];
        float2 x0a, x0b, x1a, x1b, x2a, x2b, x3a, x3b;
        float t0 = score_part(c0, b, w, x0a, x0b);
        float t1 = score_part(c1, b, w, x1a, x1b);
        float t2 = score_part(c2, b, w, x2a, x2b);
        float t3 = score_part(c3, b, w, x3a, x3b);
#pragma unroll
        for (int off = 16; off > 0; off >>= 1) {
            t0 += __shfl_xor_sync(0xFFFFFFFFu, t0, off);
            t1 += __shfl_xor_sync(0xFFFFFFFFu, t1, off);
            t2 += __shfl_xor_sync(0xFFFFFFFFu, t2, off);
            t3 += __shfl_xor_sync(0xFFFFFFFFu, t3, off);
        }
        float sv0 = __expf(t0 + cb);
        float sv1 = __expf(t1 + cb);
        float sv2 = __expf(t2 + cb);
        float sv3 = __expf(t3 + cb);
        denom += (sv0 + sv1) + (sv2 + sv3);
        o.x += sv0 * x0a.x + sv1 * x1a.x + sv2 * x2a.x + sv3 * x3a.x;
        o.y += sv0 * x0a.y + sv1 * x1a.y + sv2 * x2a.y + sv3 * x3a.y;
        o.z += sv0 * x0b.x + sv1 * x1b.x + sv2 * x2b.x + sv3 * x3b.x;
        o.w += sv0 * x0b.y + sv1 * x1b.y + sv2 * x2b.y + sv3 * x3b.y;
    }
    for (; p < end; p++) {
        int s = g_ssrc[p];
        uint4 cc = g_comb[(long long)s * 32 + lane];
        float2 xa, xb;
        float t = score_part(cc, b, w, xa, xb);
#pragma unroll
        for (int off = 16; off > 0; off >>= 1)
            t += __shfl_xor_sync(0xFFFFFFFFu, t, off);
        float sv = __expf(t + cb);
        denom += sv;
        o.x += sv * xa.x; o.y += sv * xa.y; o.z += sv * xb.x; o.w += sv * xb.y;
    }

    float rd = (end > beg) ? 1.0f / denom : 0.0f;
    float4 r = make_float4(o.x * rd, o.y * rd, o.z * rd, o.w * rd);
    *(float4*)&out[(long long)warp * DIM + lane * 4] = r;
}

// ---------------------------------------------------------------------------
extern "C" void kernel_launch(void* const* d_in, const int* in_sizes, int n_in,
                              void* d_out, int out_size) {
    const float* x       = (const float*)d_in[0];
    const int*   src_idx = (const int*)d_in[1];
    const int*   dst_idx = (const int*)d_in[2];
    const float* src_w   = (const float*)d_in[3];
    const float* src_b   = (const float*)d_in[4];
    const float* dst_w   = (const float*)d_in[5];
    const float* dst_b   = (const float*)d_in[6];
    const float* att_w   = (const float*)d_in[7];
    const float* att_b   = (const float*)d_in[8];
    float* out = (float*)d_out;

    (void)in_sizes; (void)n_in; (void)out_size;

    static cudaStream_t s2 = nullptr;
    static cudaEvent_t evFork = nullptr, evJoin = nullptr;
    if (s2 == nullptr) {
        cudaStreamCreateWithFlags(&s2, cudaStreamNonBlocking);
        cudaEventCreateWithFlags(&evFork, cudaEventDisableTiming);
        cudaEventCreateWithFlags(&evJoin, cudaEventDisableTiming);
        cudaFuncSetAttribute(gemm_tc_kernel,
                             cudaFuncAttributeMaxDynamicSharedMemorySize, GEMM_SMEM);
    }

    const int nodeWarpBlocks = (N_NODES * 32 + 255) / 256;

    // fork: GEMM branch (x + weights only; also produces comb x-halves)
    cudaEventRecord(evFork, 0);
    cudaStreamWaitEvent(s2, evFork, 0);
    dim3 gemmGrid((N_NODES + 127) / 128, 2);
    gemm_tc_kernel<<<gemmGrid, 256, GEMM_SMEM, s2>>>(x, src_w, dst_w, src_b, dst_b);
    cudaEventRecord(evJoin, s2);

    // main branch: one persistent CSR build kernel
    csr_kernel<<<CSR_BLOCKS, CSR_THREADS>>>(src_idx, dst_idx);

    // join
    cudaStreamWaitEvent(0, evJoin, 0);
    fused_out_kernel<<<nodeWarpBlocks, 256>>>(att_w, att_b, out);
}